// round 7
// baseline (speedup 1.0000x reference)
#include <cuda_runtime.h>
#include <cuda_bf16.h>
#include <cstdint>

#define HW    4096
#define NB    4
#define LOG2E 1.44269504088896340736f

// ---------------- scratch (device globals: allocation-free) ----------------
__device__ __nv_bfloat16 g_Qh[NB * HW * 64];   // [b][n][c] hi, pre-scaled by log2e
__device__ __nv_bfloat16 g_Ql[NB * HW * 64];   // [b][n][c] lo
__device__ __nv_bfloat16 g_Kh[NB * HW * 64];   // [b][n][c] hi
__device__ __nv_bfloat16 g_Kl[NB * HW * 64];   // [b][n][c] lo
__device__ __nv_bfloat16 g_Vb[NB * 64 * HW];   // [b][c][m]  (w folded in), bf16
__device__ float         g_w [NB * HW];        // w[m] = 1 + beta*edge

// ---------------- f32x2 packed-FMA helpers ----------------
__device__ __forceinline__ double dup2(float x) {
    double r; asm("mov.b64 %0, {%1,%1};" : "=d"(r) : "f"(x)); return r;
}
__device__ __forceinline__ void ffma2(double &d, double a, double b) {
    asm("fma.rn.f32x2 %0, %1, %2, %0;" : "+d"(d) : "d"(a), "d"(b));
}
__device__ __forceinline__ void unpack2(double v, float &lo, float &hi) {
    asm("mov.b64 {%0,%1}, %2;" : "=f"(lo), "=f"(hi) : "d"(v));
}
__device__ __forceinline__ float ex2f(float x) {
    float r; asm("ex2.approx.f32 %0, %1;" : "=f"(r) : "f"(x)); return r;
}
__device__ __forceinline__ uint32_t bf16x2_pack(float lo, float hi) {
    uint32_t r; asm("cvt.rn.bf16x2.f32 %0, %1, %2;" : "=r"(r) : "f"(hi), "f"(lo));
    return r;
}
__device__ __forceinline__ uint32_t smem_u32(const void* p) {
    uint32_t a;
    asm("{ .reg .u64 t; cvta.to.shared.u64 t, %1; cvt.u32.u64 %0, t; }"
        : "=r"(a) : "l"(p));
    return a;
}

#define SW128(o) ((o) ^ (((o) >> 3) & 0x70))

// ---------------- mma.sync / ldmatrix ----------------
#define LDMX4(r, addr) \
    asm volatile("ldmatrix.sync.aligned.m8n8.x4.shared.b16 {%0,%1,%2,%3}, [%4];" \
        : "=r"((r)[0]), "=r"((r)[1]), "=r"((r)[2]), "=r"((r)[3]) : "r"(addr))

#define MMA16816(d, a, b0, b1) \
    asm volatile("mma.sync.aligned.m16n8k16.row.col.f32.bf16.bf16.f32 " \
        "{%0,%1,%2,%3},{%4,%5,%6,%7},{%8,%9},{%0,%1,%2,%3};" \
        : "+f"((d)[0]), "+f"((d)[1]), "+f"((d)[2]), "+f"((d)[3]) \
        : "r"((a)[0]), "r"((a)[1]), "r"((a)[2]), "r"((a)[3]), "r"(b0), "r"(b1))

// ================= kernel 1: edge detector -> g_w =================
// 128 CTAs; each CTA: 2 image rows (128 px), 512 thr = 4 thr/px (16 ch each).
#define XT_FLOATS (64 * 4 * 66)                 // 16896
#define WS_FLOATS (64 * 9 * 32)                 // 18432
#define RED_STRIDE 34
#define RED_FLOATS (3 * 128 * RED_STRIDE)       // 13056
#define EDGE_SMEM ((XT_FLOATS + WS_FLOATS + RED_FLOATS) * 4)   // 193536 B

__global__ __launch_bounds__(512) void edge_kernel(
    const float* __restrict__ x,  const float* __restrict__ We1,
    const float* __restrict__ be1,
    const float* __restrict__ bn_w, const float* __restrict__ bn_b,
    const float* __restrict__ bn_mean, const float* __restrict__ bn_var,
    const float* __restrict__ We2, const float* __restrict__ be2,
    const float* __restrict__ beta)
{
    extern __shared__ float es[];
    float* xt  = es;                         // [64ch][4r][66c]
    float* Wsh = es + XT_FLOATS;             // [(cc*9+k)*32 + ch]
    float* red = es + XT_FLOATS + WS_FLOATS; // [3][128px][34]
    __shared__ float s_sc[32], s_sh[32], s_w2[32];

    const int tid = threadIdx.x;
    const int b   = blockIdx.y;
    const int pr0 = blockIdx.x * 2;          // image row base (2 rows per CTA)

    if (tid < 32) {
        float s = bn_w[tid] * rsqrtf(bn_var[tid] + 1e-5f);
        s_sc[tid] = s;
        s_sh[tid] = (be1[tid] - bn_mean[tid]) * s + bn_b[tid];
        s_w2[tid] = We2[tid];
    }

    for (int e = tid; e < WS_FLOATS; e += 512) {
        int ch = e & 31, rest = e >> 5;
        int k = rest % 9, cc = rest / 9;
        Wsh[e] = We1[(ch * 64 + cc) * 9 + k];
    }
    for (int e = tid; e < XT_FLOATS; e += 512) {
        int c66 = e % 66, rest = e / 66;
        int r = rest & 3, ch = rest >> 2;
        int ir = pr0 - 1 + r, ic = c66 - 1;
        float v = 0.f;
        if (ir >= 0 && ir < 64 && ic >= 0 && ic < 64)
            v = x[(size_t)(b * 64 + ch) * HW + ir * 64 + ic];
        xt[e] = v;
    }
    __syncthreads();

    const int px  = tid & 127;
    const int cu  = tid >> 7;                // channel chunk (0..3), 16 ch each
    const int pr  = px >> 6, col = px & 63;

    double acc2[16];
    #pragma unroll
    for (int i = 0; i < 16; i++) acc2[i] = 0.0;

    for (int ccl = 0; ccl < 16; ccl++) {
        const int cc = cu * 16 + ccl;
        const float* xb = &xt[(cc * 4 + pr) * 66 + col];
        float xv[9];
        #pragma unroll
        for (int ry = 0; ry < 3; ry++)
            #pragma unroll
            for (int rx = 0; rx < 3; rx++)
                xv[ry * 3 + rx] = xb[ry * 66 + rx];
        #pragma unroll
        for (int k = 0; k < 9; k++) {
            double dv = dup2(xv[k]);
            const double* wrow = (const double*)&Wsh[(cc * 9 + k) * 32];
            #pragma unroll
            for (int c2 = 0; c2 < 16; c2++) ffma2(acc2[c2], dv, wrow[c2]);
        }
    }

    if (cu != 0) {
        double* rp = (double*)&red[((cu - 1) * 128 + px) * RED_STRIDE];
        #pragma unroll
        for (int i = 0; i < 16; i++) rp[i] = acc2[i];
    }
    __syncthreads();
    if (cu == 0) {
        const double* rp1 = (const double*)&red[(px)       * RED_STRIDE];
        const double* rp2 = (const double*)&red[(128 + px) * RED_STRIDE];
        const double* rp3 = (const double*)&red[(256 + px) * RED_STRIDE];
        float e2 = be2[0];
        #pragma unroll
        for (int c2 = 0; c2 < 16; c2++) {
            float a0, a1, p0, p1;
            unpack2(acc2[c2], a0, a1);
            unpack2(rp1[c2], p0, p1); a0 += p0; a1 += p1;
            unpack2(rp2[c2], p0, p1); a0 += p0; a1 += p1;
            unpack2(rp3[c2], p0, p1); a0 += p0; a1 += p1;
            const int ch = c2 * 2;
            float r0 = fmaxf(a0 * s_sc[ch]     + s_sh[ch],     0.f);
            float r1 = fmaxf(a1 * s_sc[ch + 1] + s_sh[ch + 1], 0.f);
            e2 += s_w2[ch] * r0 + s_w2[ch + 1] * r1;
        }
        float sig = 1.f / (1.f + ex2f(-e2 * LOG2E));
        g_w[b * HW + pr0 * 64 + px] = 1.f + beta[0] * sig;
    }
}

// ================= kernel 2: QKV projections -> bf16 hi/lo =================
__global__ __launch_bounds__(256) void qkv_kernel(
    const float* __restrict__ x,
    const float* __restrict__ Wq, const float* __restrict__ bq,
    const float* __restrict__ Wk, const float* __restrict__ bk,
    const float* __restrict__ Wv, const float* __restrict__ bv)
{
    __shared__ __align__(16) float xs[64 * 64];
    __shared__ __align__(16) float WTq[32 * 64];
    __shared__ __align__(16) float WTk[32 * 64];
    __shared__ __align__(16) float WTv[32 * 64];

    const int tid = threadIdx.x;
    const int b   = blockIdx.y;
    const int n0  = blockIdx.x * 64;

    for (int e = tid; e < 4096; e += 256) {
        int c = e >> 6, j = e & 63;
        xs[c * 64 + j] = x[(size_t)(b * 64 + c) * HW + n0 + j];
    }

    const int tn = tid & 15, to = tid >> 4;
    double aq[4][2], ak[4][2], av[4][2];
    #pragma unroll
    for (int i = 0; i < 4; i++) {
        aq[i][0] = aq[i][1] = 0.0; ak[i][0] = ak[i][1] = 0.0; av[i][0] = av[i][1] = 0.0;
    }

    for (int chunk = 0; chunk < 2; chunk++) {
        __syncthreads();
        for (int e = tid; e < 2048; e += 256) {
            int o = e & 63, c = e >> 6;
            WTq[c * 64 + o] = Wq[o * 64 + chunk * 32 + c];
            WTk[c * 64 + o] = Wk[o * 64 + chunk * 32 + c];
            WTv[c * 64 + o] = Wv[o * 64 + chunk * 32 + c];
        }
        __syncthreads();
        #pragma unroll 4
        for (int cc = 0; cc < 32; cc++) {
            const float4 xv = *(const float4*)&xs[(chunk * 32 + cc) * 64 + tn * 4];
            const double2 wq = *(const double2*)&WTq[cc * 64 + to * 4];
            const double2 wk = *(const double2*)&WTk[cc * 64 + to * 4];
            const double2 wv = *(const double2*)&WTv[cc * 64 + to * 4];
            double dn[4] = {dup2(xv.x), dup2(xv.y), dup2(xv.z), dup2(xv.w)};
            #pragma unroll
            for (int jn = 0; jn < 4; jn++) {
                ffma2(aq[jn][0], dn[jn], wq.x); ffma2(aq[jn][1], dn[jn], wq.y);
                ffma2(ak[jn][0], dn[jn], wk.x); ffma2(ak[jn][1], dn[jn], wk.y);
                ffma2(av[jn][0], dn[jn], wv.x); ffma2(av[jn][1], dn[jn], wv.y);
            }
        }
    }

    const int ob = to * 4;
    float bqv[4], bkv[4], bvv[4];
    #pragma unroll
    for (int io = 0; io < 4; io++) {
        bqv[io] = bq[ob + io]; bkv[io] = bk[ob + io]; bvv[io] = bv[ob + io];
    }
    #pragma unroll
    for (int jn = 0; jn < 4; jn++) {
        const int n = n0 + tn * 4 + jn;
        float qf[4], kf[4], vf[4];
        unpack2(aq[jn][0], qf[0], qf[1]); unpack2(aq[jn][1], qf[2], qf[3]);
        unpack2(ak[jn][0], kf[0], kf[1]); unpack2(ak[jn][1], kf[2], kf[3]);
        unpack2(av[jn][0], vf[0], vf[1]); unpack2(av[jn][1], vf[2], vf[3]);
        const float wnj = g_w[b * HW + n];
        __nv_bfloat16 qh[4], ql[4], kh[4], kl[4];
        #pragma unroll
        for (int io = 0; io < 4; io++) {
            float q = (qf[io] + bqv[io]) * LOG2E;
            float k = kf[io] + bkv[io];
            qh[io] = __float2bfloat16(q);
            ql[io] = __float2bfloat16(q - __bfloat162float(qh[io]));
            kh[io] = __float2bfloat16(k);
            kl[io] = __float2bfloat16(k - __bfloat162float(kh[io]));
            g_Vb[((size_t)(b * 64 + ob + io)) * HW + n] =
                __float2bfloat16((vf[io] + bvv[io]) * wnj);
        }
        const size_t base = ((size_t)(b * HW + n)) * 64 + ob;
        *(__nv_bfloat162*)&g_Qh[base]     = __nv_bfloat162(qh[0], qh[1]);
        *(__nv_bfloat162*)&g_Qh[base + 2] = __nv_bfloat162(qh[2], qh[3]);
        *(__nv_bfloat162*)&g_Ql[base]     = __nv_bfloat162(ql[0], ql[1]);
        *(__nv_bfloat162*)&g_Ql[base + 2] = __nv_bfloat162(ql[2], ql[3]);
        *(__nv_bfloat162*)&g_Kh[base]     = __nv_bfloat162(kh[0], kh[1]);
        *(__nv_bfloat162*)&g_Kh[base + 2] = __nv_bfloat162(kh[2], kh[3]);
        *(__nv_bfloat162*)&g_Kl[base]     = __nv_bfloat162(kl[0], kl[1]);
        *(__nv_bfloat162*)&g_Kl[base + 2] = __nv_bfloat162(kl[2], kl[3]);
    }
}

// ================= kernel 3: mma.sync flash attention (16 warps) =========
// Warp (qg, half): 16 q-rows, key half `half` of every tile.
// Independent online-softmax chains per warp; single merge at the end.
#define OFF_QH 0            // 16KB
#define OFF_QL 16384        // 16KB
#define OFF_K  32768        // 2 bufs * (KH 16KB + KL 16KB)
#define OFF_V  98304        // 2 bufs * 16KB
#define OFF_AW 131072       // 2 bufs * 128 f32
#define SMEM_BYTES 132096
// epilogue overlay (after mainloop):
#define OFF_OST0 0          // 32KB [64c][128q]
#define OFF_OST1 32768      // 32KB
#define OFF_MSH  65536      // 2*128 f32
#define OFF_DSH  66560      // 2*128 f32

__global__ __launch_bounds__(512, 1) void flash_kernel(
    const float* __restrict__ x, const float* __restrict__ gamma,
    float* __restrict__ out)
{
    extern __shared__ char smem[];
    const uint32_t sbase = smem_u32(smem);
    const int tid  = threadIdx.x;
    const int lane = tid & 31, wid = tid >> 5;
    const int qg   = wid & 7;            // q-row group
    const int half = wid >> 3;           // key half (0/1)
    const int g    = lane >> 2;
    const int u    = lane & 3;
    const int q0w  = qg * 16;
    const int b    = blockIdx.y;
    const int n0   = blockIdx.x * 128;

    {
        const uint4* Qhg = (const uint4*)(g_Qh + ((size_t)(b * HW + n0)) * 64);
        const uint4* Qlg = (const uint4*)(g_Ql + ((size_t)(b * HW + n0)) * 64);
        for (int e = tid; e < 1024; e += 512) {
            int r = e >> 3, c8 = e & 7;
            uint32_t o = SW128(r * 128 + c8 * 16);
            *(uint4*)(smem + OFF_QH + o) = Qhg[e];
            *(uint4*)(smem + OFF_QL + o) = Qlg[e];
        }
        const uint4* KHg = (const uint4*)(g_Kh + ((size_t)(b * HW)) * 64);
        const uint4* KLg = (const uint4*)(g_Kl + ((size_t)(b * HW)) * 64);
        for (int e = tid; e < 1024; e += 512) {
            int r = e >> 3, c8 = e & 7;
            uint32_t o = SW128(r * 128 + c8 * 16);
            *(uint4*)(smem + OFF_K + o)         = KHg[e];
            *(uint4*)(smem + OFF_K + 16384 + o) = KLg[e];
        }
        const __nv_bfloat16* Vg = g_Vb + (size_t)b * 64 * HW;
        for (int e = tid; e < 1024; e += 512) {
            int c = e >> 4, j8 = e & 15;
            uint4 val = *(const uint4*)(Vg + (size_t)c * HW + j8 * 8);
            *(uint4*)(smem + OFF_V + (j8 >> 3) * 8192 +
                      SW128(c * 128 + (j8 & 7) * 16)) = val;
        }
        if (tid < 128) *(float*)(smem + OFF_AW + tid * 4) = fabsf(g_w[b * HW + tid]);
    }
    __syncthreads();

    uint32_t qh[4][4], ql[4][4];
    {
        const int row = q0w + (lane & 15);
        #pragma unroll
        for (int ks = 0; ks < 4; ks++) {
            const uint32_t cb = ks * 32 + (lane >> 4) * 16;
            LDMX4(qh[ks], sbase + OFF_QH + SW128(row * 128 + cb));
            LDMX4(ql[ks], sbase + OFF_QL + SW128(row * 128 + cb));
        }
    }

    float o[8][4];
    #pragma unroll
    for (int ct = 0; ct < 8; ct++)
        o[ct][0] = o[ct][1] = o[ct][2] = o[ct][3] = 0.f;
    float mrow0 = -1e30f, mrow1 = -1e30f, den0 = 0.f, den1 = 0.f;

    for (int t = 0; t < 32; t++) {
        const int buf = t & 1;

        if (t < 31) {
            const int m1 = (t + 1) * 128, nb = buf ^ 1;
            const uint4* KHg = (const uint4*)(g_Kh + ((size_t)(b * HW + m1)) * 64);
            const uint4* KLg = (const uint4*)(g_Kl + ((size_t)(b * HW + m1)) * 64);
            char* kb = smem + OFF_K + nb * 32768;
            for (int e = tid; e < 1024; e += 512) {
                int r = e >> 3, c8 = e & 7;
                uint32_t oo = SW128(r * 128 + c8 * 16);
                *(uint4*)(kb + oo)         = KHg[e];
                *(uint4*)(kb + 16384 + oo) = KLg[e];
            }
            const __nv_bfloat16* Vg = g_Vb + (size_t)b * 64 * HW + m1;
            char* vb = smem + OFF_V + nb * 16384;
            for (int e = tid; e < 1024; e += 512) {
                int c = e >> 4, j8 = e & 15;
                uint4 val = *(const uint4*)(Vg + (size_t)c * HW + j8 * 8);
                *(uint4*)(vb + (j8 >> 3) * 8192 +
                          SW128(c * 128 + (j8 & 7) * 16)) = val;
            }
            if (tid < 128)
                *(float*)(smem + OFF_AW + nb * 512 + tid * 4) =
                    fabsf(g_w[b * HW + m1 + tid]);
        }

        const uint32_t kh_b = sbase + OFF_K + buf * 32768;
        const uint32_t kl_b = kh_b + 16384;
        const float*   awp  = (const float*)(smem + OFF_AW + buf * 512);

        // ---- S = QK^T for this warp's 64 keys, hi/lo 3-pass ----
        float s[8][4];
        #pragma unroll
        for (int i = 0; i < 8; i++)
            s[i][0] = s[i][1] = s[i][2] = s[i][3] = 0.f;

        #pragma unroll
        for (int i = 0; i < 8; i++) {
            const int nt = half * 8 + i;
            const uint32_t roff = (nt * 8 + (lane & 7)) * 128 + (lane >> 3) * 16;
            uint32_t bh[8], bl[8];
            LDMX4(bh,     kh_b + SW128(roff));
            LDMX4(bh + 4, kh_b + SW128(roff + 64));
            LDMX4(bl,     kl_b + SW128(roff));
            LDMX4(bl + 4, kl_b + SW128(roff + 64));
            #pragma unroll
            for (int ks = 0; ks < 4; ks++) {
                MMA16816(s[i], qh[ks], bh[2 * ks], bh[2 * ks + 1]);
                MMA16816(s[i], qh[ks], bl[2 * ks], bl[2 * ks + 1]);
                MMA16816(s[i], ql[ks], bh[2 * ks], bh[2 * ks + 1]);
            }
        }

        // ---- online softmax (quad-local, per-warp chain) ----
        float mx0 = s[0][0], mx1 = s[0][2];
        #pragma unroll
        for (int i = 0; i < 8; i++) {
            mx0 = fmaxf(mx0, fmaxf(s[i][0], s[i][1]));
            mx1 = fmaxf(mx1, fmaxf(s[i][2], s[i][3]));
        }
        mx0 = fmaxf(mx0, __shfl_xor_sync(0xffffffffu, mx0, 1));
        mx0 = fmaxf(mx0, __shfl_xor_sync(0xffffffffu, mx0, 2));
        mx1 = fmaxf(mx1, __shfl_xor_sync(0xffffffffu, mx1, 1));
        mx1 = fmaxf(mx1, __shfl_xor_sync(0xffffffffu, mx1, 2));

        const float mn0 = fmaxf(mrow0, mx0), mn1 = fmaxf(mrow1, mx1);
        const float cr0 = ex2f(mrow0 - mn0), cr1 = ex2f(mrow1 - mn1);
        mrow0 = mn0; mrow1 = mn1;

        float ws0 = 0.f, ws1 = 0.f;
        #pragma unroll
        for (int i = 0; i < 8; i++) {
            const float2 aw = *(const float2*)&awp[half * 64 + i * 8 + 2 * u];
            s[i][0] = ex2f(s[i][0] - mn0);
            s[i][1] = ex2f(s[i][1] - mn0);
            s[i][2] = ex2f(s[i][2] - mn1);
            s[i][3] = ex2f(s[i][3] - mn1);
            ws0 += s[i][0] * aw.x + s[i][1] * aw.y;
            ws1 += s[i][2] * aw.x + s[i][3] * aw.y;
        }
        ws0 += __shfl_xor_sync(0xffffffffu, ws0, 1);
        ws0 += __shfl_xor_sync(0xffffffffu, ws0, 2);
        ws1 += __shfl_xor_sync(0xffffffffu, ws1, 1);
        ws1 += __shfl_xor_sync(0xffffffffu, ws1, 2);
        den0 = den0 * cr0 + ws0;
        den1 = den1 * cr1 + ws1;

        #pragma unroll
        for (int ct = 0; ct < 8; ct++) {
            o[ct][0] *= cr0; o[ct][1] *= cr0;
            o[ct][2] *= cr1; o[ct][3] *= cr1;
        }

        uint32_t aP[4][4];
        #pragma unroll
        for (int j = 0; j < 4; j++) {
            aP[j][0] = bf16x2_pack(s[2 * j][0],     s[2 * j][1]);
            aP[j][1] = bf16x2_pack(s[2 * j][2],     s[2 * j][3]);
            aP[j][2] = bf16x2_pack(s[2 * j + 1][0], s[2 * j + 1][1]);
            aP[j][3] = bf16x2_pack(s[2 * j + 1][2], s[2 * j + 1][3]);
        }

        const uint32_t v_b = sbase + OFF_V + buf * 16384 + half * 8192;
        #pragma unroll
        for (int ct = 0; ct < 8; ct++) {
            const uint32_t roff = (ct * 8 + (lane & 7)) * 128 + (lane >> 3) * 16;
            uint32_t vb[8];
            LDMX4(vb,     v_b + SW128(roff));
            LDMX4(vb + 4, v_b + SW128(roff + 64));
            #pragma unroll
            for (int j = 0; j < 4; j++)
                MMA16816(o[ct], aP[j], vb[2 * j], vb[2 * j + 1]);
        }
        __syncthreads();
    }

    // ---- merge the two key-half chains, stage, write ----
    const int r0 = q0w + g, r1 = q0w + g + 8;
    float* msh = (float*)(smem + OFF_MSH);
    float* dsh = (float*)(smem + OFF_DSH);
    if (u == 0) {
        msh[half * 128 + r0] = mrow0;  msh[half * 128 + r1] = mrow1;
        dsh[half * 128 + r0] = den0;   dsh[half * 128 + r1] = den1;
    }
    __syncthreads();

    const float g0 = gamma[0];
    const float mo0 = msh[(1 - half) * 128 + r0], do0 = dsh[(1 - half) * 128 + r0];
    const float mo1 = msh[(1 - half) * 128 + r1], do1 = dsh[(1 - half) * 128 + r1];
    const float mf0 = fmaxf(mrow0, mo0), mf1 = fmaxf(mrow1, mo1);
    const float sm0 = ex2f(mrow0 - mf0), sm1 = ex2f(mrow1 - mf1);
    const float df0 = den0 * sm0 + do0 * ex2f(mo0 - mf0);
    const float df1 = den1 * sm1 + do1 * ex2f(mo1 - mf1);
    const float inv0 = g0 * sm0 / df0, inv1 = g0 * sm1 / df1;

    float* Ost = (float*)(smem + (half ? OFF_OST1 : OFF_OST0));   // [64c][128q]
    #pragma unroll
    for (int ct = 0; ct < 8; ct++) {
        const int c = ct * 8 + 2 * u;
        Ost[c * 128 + r0]       = o[ct][0] * inv0;
        Ost[(c + 1) * 128 + r0] = o[ct][1] * inv0;
        Ost[c * 128 + r1]       = o[ct][2] * inv1;
        Ost[(c + 1) * 128 + r1] = o[ct][3] * inv1;
    }
    __syncthreads();

    const float* O0 = (const float*)(smem + OFF_OST0);
    const float* O1 = (const float*)(smem + OFF_OST1);
    for (int e = tid; e < 2048; e += 512) {
        const int c = e >> 5, q4 = (e & 31) * 4;
        const int idx = c * 128 + q4;
        float4 a = *(const float4*)&O0[idx];
        const float4 bb = *(const float4*)&O1[idx];
        const size_t off = (size_t)(b * 64 + c) * HW + n0 + q4;
        const float4 xv = *(const float4*)&x[off];
        a.x += bb.x + xv.x; a.y += bb.y + xv.y;
        a.z += bb.z + xv.z; a.w += bb.w + xv.w;
        *(float4*)&out[off] = a;
    }
}

// ================= launch =================
extern "C" void kernel_launch(void* const* d_in, const int* in_sizes, int n_in,
                              void* d_out, int out_size)
{
    (void)in_sizes; (void)n_in; (void)out_size;
    const float* x       = (const float*)d_in[0];
    const float* Wq      = (const float*)d_in[1];
    const float* bq      = (const float*)d_in[2];
    const float* Wk      = (const float*)d_in[3];
    const float* bk      = (const float*)d_in[4];
    const float* Wv      = (const float*)d_in[5];
    const float* bv      = (const float*)d_in[6];
    const float* We1     = (const float*)d_in[7];
    const float* be1     = (const float*)d_in[8];
    const float* bn_w    = (const float*)d_in[9];
    const float* bn_b    = (const float*)d_in[10];
    const float* bn_mean = (const float*)d_in[11];
    const float* bn_var  = (const float*)d_in[12];
    const float* We2     = (const float*)d_in[13];
    const float* be2     = (const float*)d_in[14];
    const float* gamma   = (const float*)d_in[15];
    const float* beta    = (const float*)d_in[16];
    float* out = (float*)d_out;

    cudaFuncSetAttribute(edge_kernel, cudaFuncAttributeMaxDynamicSharedMemorySize,
                         EDGE_SMEM);
    edge_kernel<<<dim3(32, NB), 512, EDGE_SMEM>>>(x, We1, be1, bn_w, bn_b,
                                                  bn_mean, bn_var, We2, be2, beta);
    qkv_kernel<<<dim3(64, NB), 256>>>(x, Wq, bq, Wk, bk, Wv, bv);

    cudaFuncSetAttribute(flash_kernel, cudaFuncAttributeMaxDynamicSharedMemorySize,
                         SMEM_BYTES);
    flash_kernel<<<dim3(32, NB), 512, SMEM_BYTES>>>(x, gamma, out);
}

// round 8
// speedup vs baseline: 1.1447x; 1.1447x over previous
#include <cuda_runtime.h>
#include <cuda_bf16.h>
#include <cstdint>

#define HW    4096
#define NB    4
#define LOG2E 1.44269504088896340736f

// ---------------- scratch (device globals: allocation-free) ----------------
__device__ __nv_bfloat16 g_Qh[NB * HW * 64];   // [b][n][c] hi, pre-scaled by log2e
__device__ __nv_bfloat16 g_Ql[NB * HW * 64];   // [b][n][c] lo
__device__ __nv_bfloat16 g_Kh[NB * HW * 64];   // [b][n][c] hi
__device__ __nv_bfloat16 g_Kl[NB * HW * 64];   // [b][n][c] lo
__device__ __nv_bfloat16 g_Vb[NB * 64 * HW];   // [b][c][m]  (w folded in), bf16
__device__ float         g_w [NB * HW];        // w[m] = 1 + beta*edge

// ---------------- f32x2 packed-FMA helpers ----------------
__device__ __forceinline__ double dup2(float x) {
    double r; asm("mov.b64 %0, {%1,%1};" : "=d"(r) : "f"(x)); return r;
}
__device__ __forceinline__ void ffma2(double &d, double a, double b) {
    asm("fma.rn.f32x2 %0, %1, %2, %0;" : "+d"(d) : "d"(a), "d"(b));
}
__device__ __forceinline__ void unpack2(double v, float &lo, float &hi) {
    asm("mov.b64 {%0,%1}, %2;" : "=f"(lo), "=f"(hi) : "d"(v));
}
__device__ __forceinline__ float ex2f(float x) {
    float r; asm("ex2.approx.f32 %0, %1;" : "=f"(r) : "f"(x)); return r;
}
__device__ __forceinline__ uint32_t bf16x2_pack(float lo, float hi) {
    uint32_t r; asm("cvt.rn.bf16x2.f32 %0, %1, %2;" : "=r"(r) : "f"(hi), "f"(lo));
    return r;
}
__device__ __forceinline__ uint32_t smem_u32(const void* p) {
    uint32_t a;
    asm("{ .reg .u64 t; cvta.to.shared.u64 t, %1; cvt.u32.u64 %0, t; }"
        : "=r"(a) : "l"(p));
    return a;
}

#define SW128(o) ((o) ^ (((o) >> 3) & 0x70))

// ---------------- mma.sync / ldmatrix ----------------
#define LDMX4(r, addr) \
    asm volatile("ldmatrix.sync.aligned.m8n8.x4.shared.b16 {%0,%1,%2,%3}, [%4];" \
        : "=r"((r)[0]), "=r"((r)[1]), "=r"((r)[2]), "=r"((r)[3]) : "r"(addr))

#define MMA16816(d, a, b0, b1) \
    asm volatile("mma.sync.aligned.m16n8k16.row.col.f32.bf16.bf16.f32 " \
        "{%0,%1,%2,%3},{%4,%5,%6,%7},{%8,%9},{%0,%1,%2,%3};" \
        : "+f"((d)[0]), "+f"((d)[1]), "+f"((d)[2]), "+f"((d)[3]) \
        : "r"((a)[0]), "r"((a)[1]), "r"((a)[2]), "r"((a)[3]), "r"(b0), "r"(b1))

// ================= kernel 1: edge detector -> g_w =================
// 64 CTAs; each CTA: 4 image rows (256 px), 512 thr = 2 thr/px.
// cu split is ACROSS warps (warps 0-7 cu0, 8-15 cu1) so every weight LDS is a
// pure warp-uniform broadcast (no bank conflicts). x halo staged as bf16.
#define XT_ELEMS (64 * 6 * 66)                  // bf16: 50688 B
#define XT_BYTES (XT_ELEMS * 2)
#define WS_FLOATS (64 * 9 * 32)                 // fp32: 73728 B
#define RED_STRIDE 34
#define RED_FLOATS (256 * RED_STRIDE)           // 34816 B
#define EDGE_SMEM (XT_BYTES + WS_FLOATS * 4 + RED_FLOATS * 4)   // 159232 B

__global__ __launch_bounds__(512) void edge_kernel(
    const float* __restrict__ x,  const float* __restrict__ We1,
    const float* __restrict__ be1,
    const float* __restrict__ bn_w, const float* __restrict__ bn_b,
    const float* __restrict__ bn_mean, const float* __restrict__ bn_var,
    const float* __restrict__ We2, const float* __restrict__ be2,
    const float* __restrict__ beta)
{
    extern __shared__ char esm[];
    __nv_bfloat16* xt = (__nv_bfloat16*)esm;                 // [64ch][6r][66c]
    float* Wsh = (float*)(esm + XT_BYTES);                   // [(cc*9+k)*32+ch]
    float* red = (float*)(esm + XT_BYTES + WS_FLOATS * 4);   // [256px][34]
    __shared__ float s_sc[32], s_sh[32], s_w2[32];

    const int tid = threadIdx.x;
    const int b   = blockIdx.y;
    const int pr0 = blockIdx.x * 4;          // image row base (4 rows per CTA)

    if (tid < 32) {
        float s = bn_w[tid] * rsqrtf(bn_var[tid] + 1e-5f);
        s_sc[tid] = s;
        s_sh[tid] = (be1[tid] - bn_mean[tid]) * s + bn_b[tid];
        s_w2[tid] = We2[tid];
    }

    // weights transposed: Wsh[(cc*9+k)*32+ch] = We1[ch][cc][k]
    for (int e = tid; e < WS_FLOATS; e += 512) {
        int ch = e & 31, rest = e >> 5;
        int k = rest % 9, cc = rest / 9;
        Wsh[e] = We1[(ch * 64 + cc) * 9 + k];
    }
    // x halo (6 rows incl. top/bottom halo), zero-padded borders, bf16
    for (int e = tid; e < XT_ELEMS; e += 512) {
        int c66 = e % 66, rest = e / 66;
        int r = rest % 6, ch = rest / 6;
        int ir = pr0 - 1 + r, ic = c66 - 1;
        float v = 0.f;
        if (ir >= 0 && ir < 64 && ic >= 0 && ic < 64)
            v = x[(size_t)(b * 64 + ch) * HW + ir * 64 + ic];
        xt[e] = __float2bfloat16(v);
    }
    __syncthreads();

    const int wid  = tid >> 5, lane = tid & 31;
    const int cu   = wid >> 3;               // 0 (warps 0-7) / 1 (warps 8-15)
    const int px   = (wid & 7) * 32 + lane;  // 0..255
    const int pr   = px >> 6, col = px & 63;

    double acc2[16];
    #pragma unroll
    for (int i = 0; i < 16; i++) acc2[i] = 0.0;

    for (int ccl = 0; ccl < 32; ccl++) {
        const int cc = cu * 32 + ccl;
        const __nv_bfloat16* xb = &xt[(cc * 6 + pr) * 66 + col];
        float xv[9];
        #pragma unroll
        for (int ry = 0; ry < 3; ry++)
            #pragma unroll
            for (int rx = 0; rx < 3; rx++)
                xv[ry * 3 + rx] = __bfloat162float(xb[ry * 66 + rx]);
        #pragma unroll
        for (int k = 0; k < 9; k++) {
            double dv = dup2(xv[k]);
            const double* wrow = (const double*)&Wsh[(cc * 9 + k) * 32];
            #pragma unroll
            for (int c2 = 0; c2 < 16; c2++) ffma2(acc2[c2], dv, wrow[c2]);
        }
    }

    // cu1 warps park partials in smem; cu0 warps finish
    if (cu == 1) {
        double* rp = (double*)&red[px * RED_STRIDE];
        #pragma unroll
        for (int i = 0; i < 16; i++) rp[i] = acc2[i];
    }
    __syncthreads();
    if (cu == 0) {
        const double* rp = (const double*)&red[px * RED_STRIDE];
        float e2 = be2[0];
        #pragma unroll
        for (int c2 = 0; c2 < 16; c2++) {
            float a0, a1, p0, p1;
            unpack2(acc2[c2], a0, a1);
            unpack2(rp[c2],   p0, p1);
            a0 += p0; a1 += p1;
            const int ch = c2 * 2;
            float r0 = fmaxf(a0 * s_sc[ch]     + s_sh[ch],     0.f);
            float r1 = fmaxf(a1 * s_sc[ch + 1] + s_sh[ch + 1], 0.f);
            e2 += s_w2[ch] * r0 + s_w2[ch + 1] * r1;
        }
        float sig = 1.f / (1.f + ex2f(-e2 * LOG2E));
        g_w[b * HW + pr0 * 64 + px] = 1.f + beta[0] * sig;
    }
}

// ================= kernel 2: QKV projections -> bf16 hi/lo =================
__global__ __launch_bounds__(256) void qkv_kernel(
    const float* __restrict__ x,
    const float* __restrict__ Wq, const float* __restrict__ bq,
    const float* __restrict__ Wk, const float* __restrict__ bk,
    const float* __restrict__ Wv, const float* __restrict__ bv)
{
    __shared__ __align__(16) float xs[64 * 64];
    __shared__ __align__(16) float WTq[32 * 64];
    __shared__ __align__(16) float WTk[32 * 64];
    __shared__ __align__(16) float WTv[32 * 64];

    const int tid = threadIdx.x;
    const int b   = blockIdx.y;
    const int n0  = blockIdx.x * 64;

    for (int e = tid; e < 4096; e += 256) {
        int c = e >> 6, j = e & 63;
        xs[c * 64 + j] = x[(size_t)(b * 64 + c) * HW + n0 + j];
    }

    const int tn = tid & 15, to = tid >> 4;
    double aq[4][2], ak[4][2], av[4][2];
    #pragma unroll
    for (int i = 0; i < 4; i++) {
        aq[i][0] = aq[i][1] = 0.0; ak[i][0] = ak[i][1] = 0.0; av[i][0] = av[i][1] = 0.0;
    }

    for (int chunk = 0; chunk < 2; chunk++) {
        __syncthreads();
        for (int e = tid; e < 2048; e += 256) {
            int o = e & 63, c = e >> 6;
            WTq[c * 64 + o] = Wq[o * 64 + chunk * 32 + c];
            WTk[c * 64 + o] = Wk[o * 64 + chunk * 32 + c];
            WTv[c * 64 + o] = Wv[o * 64 + chunk * 32 + c];
        }
        __syncthreads();
        #pragma unroll 4
        for (int cc = 0; cc < 32; cc++) {
            const float4 xv = *(const float4*)&xs[(chunk * 32 + cc) * 64 + tn * 4];
            const double2 wq = *(const double2*)&WTq[cc * 64 + to * 4];
            const double2 wk = *(const double2*)&WTk[cc * 64 + to * 4];
            const double2 wv = *(const double2*)&WTv[cc * 64 + to * 4];
            double dn[4] = {dup2(xv.x), dup2(xv.y), dup2(xv.z), dup2(xv.w)};
            #pragma unroll
            for (int jn = 0; jn < 4; jn++) {
                ffma2(aq[jn][0], dn[jn], wq.x); ffma2(aq[jn][1], dn[jn], wq.y);
                ffma2(ak[jn][0], dn[jn], wk.x); ffma2(ak[jn][1], dn[jn], wk.y);
                ffma2(av[jn][0], dn[jn], wv.x); ffma2(av[jn][1], dn[jn], wv.y);
            }
        }
    }

    const int ob = to * 4;
    float bqv[4], bkv[4], bvv[4];
    #pragma unroll
    for (int io = 0; io < 4; io++) {
        bqv[io] = bq[ob + io]; bkv[io] = bk[ob + io]; bvv[io] = bv[ob + io];
    }
    #pragma unroll
    for (int jn = 0; jn < 4; jn++) {
        const int n = n0 + tn * 4 + jn;
        float qf[4], kf[4], vf[4];
        unpack2(aq[jn][0], qf[0], qf[1]); unpack2(aq[jn][1], qf[2], qf[3]);
        unpack2(ak[jn][0], kf[0], kf[1]); unpack2(ak[jn][1], kf[2], kf[3]);
        unpack2(av[jn][0], vf[0], vf[1]); unpack2(av[jn][1], vf[2], vf[3]);
        const float wnj = g_w[b * HW + n];
        __nv_bfloat16 qh[4], ql[4], kh[4], kl[4];
        #pragma unroll
        for (int io = 0; io < 4; io++) {
            float q = (qf[io] + bqv[io]) * LOG2E;
            float k = kf[io] + bkv[io];
            qh[io] = __float2bfloat16(q);
            ql[io] = __float2bfloat16(q - __bfloat162float(qh[io]));
            kh[io] = __float2bfloat16(k);
            kl[io] = __float2bfloat16(k - __bfloat162float(kh[io]));
            g_Vb[((size_t)(b * 64 + ob + io)) * HW + n] =
                __float2bfloat16((vf[io] + bvv[io]) * wnj);
        }
        const size_t base = ((size_t)(b * HW + n)) * 64 + ob;
        *(__nv_bfloat162*)&g_Qh[base]     = __nv_bfloat162(qh[0], qh[1]);
        *(__nv_bfloat162*)&g_Qh[base + 2] = __nv_bfloat162(qh[2], qh[3]);
        *(__nv_bfloat162*)&g_Ql[base]     = __nv_bfloat162(ql[0], ql[1]);
        *(__nv_bfloat162*)&g_Ql[base + 2] = __nv_bfloat162(ql[2], ql[3]);
        *(__nv_bfloat162*)&g_Kh[base]     = __nv_bfloat162(kh[0], kh[1]);
        *(__nv_bfloat162*)&g_Kh[base + 2] = __nv_bfloat162(kh[2], kh[3]);
        *(__nv_bfloat162*)&g_Kl[base]     = __nv_bfloat162(kl[0], kl[1]);
        *(__nv_bfloat162*)&g_Kl[base + 2] = __nv_bfloat162(kl[2], kl[3]);
    }
}

// ================= kernel 3: mma.sync flash attention (R6 config) =========
#define OFF_QH 0            // 16KB  [128 tok][64c] bf16 SW128
#define OFF_QL 16384        // 16KB
#define OFF_K  32768        // 2 bufs * (KH 16KB + KL 16KB) = 64KB
#define OFF_V  98304        // 2 bufs * 16KB
#define OFF_AW 131072       // 2 bufs * 128 f32
#define SMEM_BYTES 132096

__global__ __launch_bounds__(256, 1) void flash_kernel(
    const float* __restrict__ x, const float* __restrict__ gamma,
    float* __restrict__ out)
{
    extern __shared__ char smem[];
    const uint32_t sbase = smem_u32(smem);
    const int tid  = threadIdx.x;
    const int lane = tid & 31, wid = tid >> 5;
    const int g    = lane >> 2;
    const int u    = lane & 3;
    const int q0w  = wid * 16;
    const int b    = blockIdx.y;
    const int n0   = blockIdx.x * 128;

    {
        const uint4* Qhg = (const uint4*)(g_Qh + ((size_t)(b * HW + n0)) * 64);
        const uint4* Qlg = (const uint4*)(g_Ql + ((size_t)(b * HW + n0)) * 64);
        for (int e = tid; e < 1024; e += 256) {
            int r = e >> 3, c8 = e & 7;
            uint32_t o = SW128(r * 128 + c8 * 16);
            *(uint4*)(smem + OFF_QH + o) = Qhg[e];
            *(uint4*)(smem + OFF_QL + o) = Qlg[e];
        }
        const uint4* KHg = (const uint4*)(g_Kh + ((size_t)(b * HW)) * 64);
        const uint4* KLg = (const uint4*)(g_Kl + ((size_t)(b * HW)) * 64);
        for (int e = tid; e < 1024; e += 256) {
            int r = e >> 3, c8 = e & 7;
            uint32_t o = SW128(r * 128 + c8 * 16);
            *(uint4*)(smem + OFF_K + o)         = KHg[e];
            *(uint4*)(smem + OFF_K + 16384 + o) = KLg[e];
        }
        const __nv_bfloat16* Vg = g_Vb + (size_t)b * 64 * HW;
        for (int e = tid; e < 1024; e += 256) {
            int c = e >> 4, j8 = e & 15;
            uint4 val = *(const uint4*)(Vg + (size_t)c * HW + j8 * 8);
            *(uint4*)(smem + OFF_V + (j8 >> 3) * 8192 +
                      SW128(c * 128 + (j8 & 7) * 16)) = val;
        }
        if (tid < 128) *(float*)(smem + OFF_AW + tid * 4) = fabsf(g_w[b * HW + tid]);
    }
    __syncthreads();

    uint32_t qh[4][4], ql[4][4];
    {
        const int row = q0w + (lane & 15);
        #pragma unroll
        for (int ks = 0; ks < 4; ks++) {
            const uint32_t cb = ks * 32 + (lane >> 4) * 16;
            LDMX4(qh[ks], sbase + OFF_QH + SW128(row * 128 + cb));
            LDMX4(ql[ks], sbase + OFF_QL + SW128(row * 128 + cb));
        }
    }

    float o[8][4];
    #pragma unroll
    for (int ct = 0; ct < 8; ct++)
        o[ct][0] = o[ct][1] = o[ct][2] = o[ct][3] = 0.f;
    float mrow0 = -1e30f, mrow1 = -1e30f, den0 = 0.f, den1 = 0.f;

    for (int t = 0; t < 32; t++) {
        const int buf = t & 1;

        if (t < 31) {
            const int m1 = (t + 1) * 128, nb = buf ^ 1;
            const uint4* KHg = (const uint4*)(g_Kh + ((size_t)(b * HW + m1)) * 64);
            const uint4* KLg = (const uint4*)(g_Kl + ((size_t)(b * HW + m1)) * 64);
            char* kb = smem + OFF_K + nb * 32768;
            for (int e = tid; e < 1024; e += 256) {
                int r = e >> 3, c8 = e & 7;
                uint32_t oo = SW128(r * 128 + c8 * 16);
                *(uint4*)(kb + oo)         = KHg[e];
                *(uint4*)(kb + 16384 + oo) = KLg[e];
            }
            const __nv_bfloat16* Vg = g_Vb + (size_t)b * 64 * HW + m1;
            char* vb = smem + OFF_V + nb * 16384;
            for (int e = tid; e < 1024; e += 256) {
                int c = e >> 4, j8 = e & 15;
                uint4 val = *(const uint4*)(Vg + (size_t)c * HW + j8 * 8);
                *(uint4*)(vb + (j8 >> 3) * 8192 +
                          SW128(c * 128 + (j8 & 7) * 16)) = val;
            }
            if (tid < 128)
                *(float*)(smem + OFF_AW + nb * 512 + tid * 4) =
                    fabsf(g_w[b * HW + m1 + tid]);
        }

        const uint32_t kh_b = sbase + OFF_K + buf * 32768;
        const uint32_t kl_b = kh_b + 16384;
        const float*   awp  = (const float*)(smem + OFF_AW + buf * 512);

        #pragma unroll
        for (int sub = 0; sub < 2; sub++) {
            float s[8][4];
            #pragma unroll
            for (int i = 0; i < 8; i++)
                s[i][0] = s[i][1] = s[i][2] = s[i][3] = 0.f;

            #pragma unroll
            for (int i = 0; i < 8; i++) {
                const int nt = sub * 8 + i;
                const uint32_t roff = (nt * 8 + (lane & 7)) * 128 + (lane >> 3) * 16;
                uint32_t bh[8], bl[8];
                LDMX4(bh,     kh_b + SW128(roff));
                LDMX4(bh + 4, kh_b + SW128(roff + 64));
                LDMX4(bl,     kl_b + SW128(roff));
                LDMX4(bl + 4, kl_b + SW128(roff + 64));
                #pragma unroll
                for (int ks = 0; ks < 4; ks++) {
                    MMA16816(s[i], qh[ks], bh[2 * ks], bh[2 * ks + 1]);
                    MMA16816(s[i], qh[ks], bl[2 * ks], bl[2 * ks + 1]);
                    MMA16816(s[i], ql[ks], bh[2 * ks], bh[2 * ks + 1]);
                }
            }

            float mx0 = s[0][0], mx1 = s[0][2];
            #pragma unroll
            for (int i = 0; i < 8; i++) {
                mx0 = fmaxf(mx0, fmaxf(s[i][0], s[i][1]));
                mx1 = fmaxf(mx1, fmaxf(s[i][2], s[i][3]));
            }
            mx0 = fmaxf(mx0, __shfl_xor_sync(0xffffffffu, mx0, 1));
            mx0 = fmaxf(mx0, __shfl_xor_sync(0xffffffffu, mx0, 2));
            mx1 = fmaxf(mx1, __shfl_xor_sync(0xffffffffu, mx1, 1));
            mx1 = fmaxf(mx1, __shfl_xor_sync(0xffffffffu, mx1, 2));

            const float mn0 = fmaxf(mrow0, mx0), mn1 = fmaxf(mrow1, mx1);
            const float cr0 = ex2f(mrow0 - mn0), cr1 = ex2f(mrow1 - mn1);
            mrow0 = mn0; mrow1 = mn1;

            float ws0 = 0.f, ws1 = 0.f;
            #pragma unroll
            for (int i = 0; i < 8; i++) {
                const float2 aw = *(const float2*)&awp[sub * 64 + i * 8 + 2 * u];
                s[i][0] = ex2f(s[i][0] - mn0);
                s[i][1] = ex2f(s[i][1] - mn0);
                s[i][2] = ex2f(s[i][2] - mn1);
                s[i][3] = ex2f(s[i][3] - mn1);
                ws0 += s[i][0] * aw.x + s[i][1] * aw.y;
                ws1 += s[i][2] * aw.x + s[i][3] * aw.y;
            }
            ws0 += __shfl_xor_sync(0xffffffffu, ws0, 1);
            ws0 += __shfl_xor_sync(0xffffffffu, ws0, 2);
            ws1 += __shfl_xor_sync(0xffffffffu, ws1, 1);
            ws1 += __shfl_xor_sync(0xffffffffu, ws1, 2);
            den0 = den0 * cr0 + ws0;
            den1 = den1 * cr1 + ws1;

            #pragma unroll
            for (int ct = 0; ct < 8; ct++) {
                o[ct][0] *= cr0; o[ct][1] *= cr0;
                o[ct][2] *= cr1; o[ct][3] *= cr1;
            }

            uint32_t aP[4][4];
            #pragma unroll
            for (int j = 0; j < 4; j++) {
                aP[j][0] = bf16x2_pack(s[2 * j][0],     s[2 * j][1]);
                aP[j][1] = bf16x2_pack(s[2 * j][2],     s[2 * j][3]);
                aP[j][2] = bf16x2_pack(s[2 * j + 1][0], s[2 * j + 1][1]);
                aP[j][3] = bf16x2_pack(s[2 * j + 1][2], s[2 * j + 1][3]);
            }

            const uint32_t v_b = sbase + OFF_V + buf * 16384 + sub * 8192;
            #pragma unroll
            for (int ct = 0; ct < 8; ct++) {
                const uint32_t roff = (ct * 8 + (lane & 7)) * 128 + (lane >> 3) * 16;
                uint32_t vb[8];
                LDMX4(vb,     v_b + SW128(roff));
                LDMX4(vb + 4, v_b + SW128(roff + 64));
                #pragma unroll
                for (int j = 0; j < 4; j++)
                    MMA16816(o[ct], aP[j], vb[2 * j], vb[2 * j + 1]);
            }
        }
        __syncthreads();
    }

    const float g0 = gamma[0];
    const float inv0 = g0 / den0, inv1 = g0 / den1;
    float* Ost = (float*)smem;    // [64 c][128 q]
    #pragma unroll
    for (int ct = 0; ct < 8; ct++) {
        const int c = ct * 8 + 2 * u;
        Ost[c * 128 + q0w + g]             = o[ct][0] * inv0;
        Ost[(c + 1) * 128 + q0w + g]       = o[ct][1] * inv0;
        Ost[c * 128 + q0w + g + 8]         = o[ct][2] * inv1;
        Ost[(c + 1) * 128 + q0w + g + 8]   = o[ct][3] * inv1;
    }
    __syncthreads();
    for (int e = tid; e < 2048; e += 256) {
        const int c = e >> 5, q4 = (e & 31) * 4;
        float4 ov = *(float4*)&Ost[c * 128 + q4];
        const size_t off = (size_t)(b * 64 + c) * HW + n0 + q4;
        const float4 xv = *(const float4*)&x[off];
        ov.x += xv.x; ov.y += xv.y; ov.z += xv.z; ov.w += xv.w;
        *(float4*)&out[off] = ov;
    }
}

// ================= launch =================
extern "C" void kernel_launch(void* const* d_in, const int* in_sizes, int n_in,
                              void* d_out, int out_size)
{
    (void)in_sizes; (void)n_in; (void)out_size;
    const float* x       = (const float*)d_in[0];
    const float* Wq      = (const float*)d_in[1];
    const float* bq      = (const float*)d_in[2];
    const float* Wk      = (const float*)d_in[3];
    const float* bk      = (const float*)d_in[4];
    const float* Wv      = (const float*)d_in[5];
    const float* bv      = (const float*)d_in[6];
    const float* We1     = (const float*)d_in[7];
    const float* be1     = (const float*)d_in[8];
    const float* bn_w    = (const float*)d_in[9];
    const float* bn_b    = (const float*)d_in[10];
    const float* bn_mean = (const float*)d_in[11];
    const float* bn_var  = (const float*)d_in[12];
    const float* We2     = (const float*)d_in[13];
    const float* be2     = (const float*)d_in[14];
    const float* gamma   = (const float*)d_in[15];
    const float* beta    = (const float*)d_in[16];
    float* out = (float*)d_out;

    cudaFuncSetAttribute(edge_kernel, cudaFuncAttributeMaxDynamicSharedMemorySize,
                         EDGE_SMEM);
    edge_kernel<<<dim3(16, NB), 512, EDGE_SMEM>>>(x, We1, be1, bn_w, bn_b,
                                                  bn_mean, bn_var, We2, be2, beta);
    qkv_kernel<<<dim3(64, NB), 256>>>(x, Wq, bq, Wk, bk, Wv, bv);

    cudaFuncSetAttribute(flash_kernel, cudaFuncAttributeMaxDynamicSharedMemorySize,
                         SMEM_BYTES);
    flash_kernel<<<dim3(32, NB), 256, SMEM_BYTES>>>(x, gamma, out);
}

// round 9
// speedup vs baseline: 1.4901x; 1.3018x over previous
#include <cuda_runtime.h>
#include <cuda_bf16.h>
#include <cstdint>

#define HW    4096
#define NB    4
#define LOG2E 1.44269504088896340736f

// ---------------- scratch (device globals: allocation-free) ----------------
__device__ __nv_bfloat16 g_Qh[NB * HW * 64];   // [b][n][c] hi, pre-scaled by log2e
__device__ __nv_bfloat16 g_Ql[NB * HW * 64];   // [b][n][c] lo
__device__ __nv_bfloat16 g_Kh[NB * HW * 64];   // [b][n][c] hi
__device__ __nv_bfloat16 g_Kl[NB * HW * 64];   // [b][n][c] lo
__device__ __nv_bfloat16 g_Vb[NB * 64 * HW];   // [b][c][m]  (w folded in), bf16
__device__ float         g_w [NB * HW];        // w[m] = 1 + beta*edge

// ---------------- f32x2 packed-FMA helpers ----------------
__device__ __forceinline__ double dup2(float x) {
    double r; asm("mov.b64 %0, {%1,%1};" : "=d"(r) : "f"(x)); return r;
}
__device__ __forceinline__ void ffma2(double &d, double a, double b) {
    asm("fma.rn.f32x2 %0, %1, %2, %0;" : "+d"(d) : "d"(a), "d"(b));
}
__device__ __forceinline__ void unpack2(double v, float &lo, float &hi) {
    asm("mov.b64 {%0,%1}, %2;" : "=f"(lo), "=f"(hi) : "d"(v));
}
__device__ __forceinline__ float ex2f(float x) {
    float r; asm("ex2.approx.f32 %0, %1;" : "=f"(r) : "f"(x)); return r;
}
__device__ __forceinline__ uint32_t bf16x2_pack(float lo, float hi) {
    uint32_t r; asm("cvt.rn.bf16x2.f32 %0, %1, %2;" : "=r"(r) : "f"(hi), "f"(lo));
    return r;
}
__device__ __forceinline__ uint32_t smem_u32(const void* p) {
    uint32_t a;
    asm("{ .reg .u64 t; cvta.to.shared.u64 t, %1; cvt.u32.u64 %0, t; }"
        : "=r"(a) : "l"(p));
    return a;
}

#define SW128(o) ((o) ^ (((o) >> 3) & 0x70))

// ---------------- mma.sync / ldmatrix ----------------
#define LDMX4(r, addr) \
    asm volatile("ldmatrix.sync.aligned.m8n8.x4.shared.b16 {%0,%1,%2,%3}, [%4];" \
        : "=r"((r)[0]), "=r"((r)[1]), "=r"((r)[2]), "=r"((r)[3]) : "r"(addr))

#define MMA16816(d, a, b0, b1) \
    asm volatile("mma.sync.aligned.m16n8k16.row.col.f32.bf16.bf16.f32 " \
        "{%0,%1,%2,%3},{%4,%5,%6,%7},{%8,%9},{%0,%1,%2,%3};" \
        : "+f"((d)[0]), "+f"((d)[1]), "+f"((d)[2]), "+f"((d)[3]) \
        : "r"((a)[0]), "r"((a)[1]), "r"((a)[2]), "r"((a)[3]), "r"(b0), "r"(b1))

// ================= kernel 1: edge detector -> g_w (R6 proven config) ======
// 128 CTAs; each CTA: 2 image rows (128 px), 256 thr = 2 thr/px (32 ch each).
#define XT_FLOATS (64 * 4 * 66)                 // 16896
#define WS_FLOATS (64 * 9 * 32)                 // 18432
#define RED_STRIDE 34
#define RED_FLOATS (128 * RED_STRIDE)           // 4352
#define EDGE_SMEM ((XT_FLOATS + WS_FLOATS + RED_FLOATS) * 4)   // 158720 B

__global__ __launch_bounds__(256) void edge_kernel(
    const float* __restrict__ x,  const float* __restrict__ We1,
    const float* __restrict__ be1,
    const float* __restrict__ bn_w, const float* __restrict__ bn_b,
    const float* __restrict__ bn_mean, const float* __restrict__ bn_var,
    const float* __restrict__ We2, const float* __restrict__ be2,
    const float* __restrict__ beta)
{
    extern __shared__ float es[];
    float* xt  = es;                         // [64ch][4r][66c]
    float* Wsh = es + XT_FLOATS;             // [(cc*9+k)*32 + ch]
    float* red = es + XT_FLOATS + WS_FLOATS; // [128px][34]
    __shared__ float s_sc[32], s_sh[32], s_w2[32];

    const int tid = threadIdx.x;
    const int b   = blockIdx.y;
    const int pr0 = blockIdx.x * 2;          // image row base (2 rows per CTA)

    if (tid < 32) {
        float s = bn_w[tid] * rsqrtf(bn_var[tid] + 1e-5f);
        s_sc[tid] = s;
        s_sh[tid] = (be1[tid] - bn_mean[tid]) * s + bn_b[tid];
        s_w2[tid] = We2[tid];
    }

    for (int e = tid; e < WS_FLOATS; e += 256) {
        int ch = e & 31, rest = e >> 5;
        int k = rest % 9, cc = rest / 9;
        Wsh[e] = We1[(ch * 64 + cc) * 9 + k];
    }
    for (int e = tid; e < XT_FLOATS; e += 256) {
        int c66 = e % 66, rest = e / 66;
        int r = rest & 3, ch = rest >> 2;
        int ir = pr0 - 1 + r, ic = c66 - 1;
        float v = 0.f;
        if (ir >= 0 && ir < 64 && ic >= 0 && ic < 64)
            v = x[(size_t)(b * 64 + ch) * HW + ir * 64 + ic];
        xt[e] = v;
    }
    __syncthreads();

    const int px  = tid & 127;
    const int cu  = tid >> 7;                // channel chunk (0/1)
    const int pr  = px >> 6, col = px & 63;

    double acc2[16];
    #pragma unroll
    for (int i = 0; i < 16; i++) acc2[i] = 0.0;

    for (int ccl = 0; ccl < 32; ccl++) {
        const int cc = cu * 32 + ccl;
        const float* xb = &xt[(cc * 4 + pr) * 66 + col];
        float xv[9];
        #pragma unroll
        for (int ry = 0; ry < 3; ry++)
            #pragma unroll
            for (int rx = 0; rx < 3; rx++)
                xv[ry * 3 + rx] = xb[ry * 66 + rx];
        #pragma unroll
        for (int k = 0; k < 9; k++) {
            double dv = dup2(xv[k]);
            const double* wrow = (const double*)&Wsh[(cc * 9 + k) * 32];
            #pragma unroll
            for (int c2 = 0; c2 < 16; c2++) ffma2(acc2[c2], dv, wrow[c2]);
        }
    }

    if (cu == 1) {
        double* rp = (double*)&red[px * RED_STRIDE];
        #pragma unroll
        for (int i = 0; i < 16; i++) rp[i] = acc2[i];
    }
    __syncthreads();
    if (cu == 0) {
        const double* rp = (const double*)&red[px * RED_STRIDE];
        float e2 = be2[0];
        #pragma unroll
        for (int c2 = 0; c2 < 16; c2++) {
            float a0, a1, p0, p1;
            unpack2(acc2[c2], a0, a1);
            unpack2(rp[c2],   p0, p1);
            a0 += p0; a1 += p1;
            const int ch = c2 * 2;
            float r0 = fmaxf(a0 * s_sc[ch]     + s_sh[ch],     0.f);
            float r1 = fmaxf(a1 * s_sc[ch + 1] + s_sh[ch + 1], 0.f);
            e2 += s_w2[ch] * r0 + s_w2[ch + 1] * r1;
        }
        float sig = 1.f / (1.f + ex2f(-e2 * LOG2E));
        g_w[b * HW + pr0 * 64 + px] = 1.f + beta[0] * sig;
    }
}

// ================= kernel 2: QKV projections -> bf16 hi/lo =================
__global__ __launch_bounds__(256) void qkv_kernel(
    const float* __restrict__ x,
    const float* __restrict__ Wq, const float* __restrict__ bq,
    const float* __restrict__ Wk, const float* __restrict__ bk,
    const float* __restrict__ Wv, const float* __restrict__ bv)
{
    __shared__ __align__(16) float xs[64 * 64];
    __shared__ __align__(16) float WTq[32 * 64];
    __shared__ __align__(16) float WTk[32 * 64];
    __shared__ __align__(16) float WTv[32 * 64];

    const int tid = threadIdx.x;
    const int b   = blockIdx.y;
    const int n0  = blockIdx.x * 64;

    for (int e = tid; e < 4096; e += 256) {
        int c = e >> 6, j = e & 63;
        xs[c * 64 + j] = x[(size_t)(b * 64 + c) * HW + n0 + j];
    }

    const int tn = tid & 15, to = tid >> 4;
    double aq[4][2], ak[4][2], av[4][2];
    #pragma unroll
    for (int i = 0; i < 4; i++) {
        aq[i][0] = aq[i][1] = 0.0; ak[i][0] = ak[i][1] = 0.0; av[i][0] = av[i][1] = 0.0;
    }

    for (int chunk = 0; chunk < 2; chunk++) {
        __syncthreads();
        for (int e = tid; e < 2048; e += 256) {
            int o = e & 63, c = e >> 6;
            WTq[c * 64 + o] = Wq[o * 64 + chunk * 32 + c];
            WTk[c * 64 + o] = Wk[o * 64 + chunk * 32 + c];
            WTv[c * 64 + o] = Wv[o * 64 + chunk * 32 + c];
        }
        __syncthreads();
        #pragma unroll 4
        for (int cc = 0; cc < 32; cc++) {
            const float4 xv = *(const float4*)&xs[(chunk * 32 + cc) * 64 + tn * 4];
            const double2 wq = *(const double2*)&WTq[cc * 64 + to * 4];
            const double2 wk = *(const double2*)&WTk[cc * 64 + to * 4];
            const double2 wv = *(const double2*)&WTv[cc * 64 + to * 4];
            double dn[4] = {dup2(xv.x), dup2(xv.y), dup2(xv.z), dup2(xv.w)};
            #pragma unroll
            for (int jn = 0; jn < 4; jn++) {
                ffma2(aq[jn][0], dn[jn], wq.x); ffma2(aq[jn][1], dn[jn], wq.y);
                ffma2(ak[jn][0], dn[jn], wk.x); ffma2(ak[jn][1], dn[jn], wk.y);
                ffma2(av[jn][0], dn[jn], wv.x); ffma2(av[jn][1], dn[jn], wv.y);
            }
        }
    }

    const int ob = to * 4;
    float bqv[4], bkv[4], bvv[4];
    #pragma unroll
    for (int io = 0; io < 4; io++) {
        bqv[io] = bq[ob + io]; bkv[io] = bk[ob + io]; bvv[io] = bv[ob + io];
    }
    #pragma unroll
    for (int jn = 0; jn < 4; jn++) {
        const int n = n0 + tn * 4 + jn;
        float qf[4], kf[4], vf[4];
        unpack2(aq[jn][0], qf[0], qf[1]); unpack2(aq[jn][1], qf[2], qf[3]);
        unpack2(ak[jn][0], kf[0], kf[1]); unpack2(ak[jn][1], kf[2], kf[3]);
        unpack2(av[jn][0], vf[0], vf[1]); unpack2(av[jn][1], vf[2], vf[3]);
        const float wnj = g_w[b * HW + n];
        __nv_bfloat16 qh[4], ql[4], kh[4], kl[4];
        #pragma unroll
        for (int io = 0; io < 4; io++) {
            float q = (qf[io] + bqv[io]) * LOG2E;
            float k = kf[io] + bkv[io];
            qh[io] = __float2bfloat16(q);
            ql[io] = __float2bfloat16(q - __bfloat162float(qh[io]));
            kh[io] = __float2bfloat16(k);
            kl[io] = __float2bfloat16(k - __bfloat162float(kh[io]));
            g_Vb[((size_t)(b * 64 + ob + io)) * HW + n] =
                __float2bfloat16((vf[io] + bvv[io]) * wnj);
        }
        const size_t base = ((size_t)(b * HW + n)) * 64 + ob;
        *(__nv_bfloat162*)&g_Qh[base]     = __nv_bfloat162(qh[0], qh[1]);
        *(__nv_bfloat162*)&g_Qh[base + 2] = __nv_bfloat162(qh[2], qh[3]);
        *(__nv_bfloat162*)&g_Ql[base]     = __nv_bfloat162(ql[0], ql[1]);
        *(__nv_bfloat162*)&g_Ql[base + 2] = __nv_bfloat162(ql[2], ql[3]);
        *(__nv_bfloat162*)&g_Kh[base]     = __nv_bfloat162(kh[0], kh[1]);
        *(__nv_bfloat162*)&g_Kh[base + 2] = __nv_bfloat162(kh[2], kh[3]);
        *(__nv_bfloat162*)&g_Kl[base]     = __nv_bfloat162(kl[0], kl[1]);
        *(__nv_bfloat162*)&g_Kl[base + 2] = __nv_bfloat162(kl[2], kl[3]);
    }
}

// ================= kernel 3: flash attention, 16 warps, no-spill ==========
// Warp (qg, half): 16 q-rows, key half `half` of every tile; Q fragments are
// re-loaded from smem EACH TILE (short live range -> no register spills).
#define OFF_QH 0            // 16KB
#define OFF_QL 16384        // 16KB
#define OFF_K  32768        // 2 bufs * (KH 16KB + KL 16KB)
#define OFF_V  98304        // 2 bufs * 16KB
#define OFF_AW 131072       // 2 bufs * 128 f32
#define SMEM_BYTES 132096
// epilogue overlay:
#define OFF_OST0 0
#define OFF_OST1 32768
#define OFF_MSH  65536
#define OFF_DSH  66560

__global__ __launch_bounds__(512, 1) void flash_kernel(
    const float* __restrict__ x, const float* __restrict__ gamma,
    float* __restrict__ out)
{
    extern __shared__ char smem[];
    const uint32_t sbase = smem_u32(smem);
    const int tid  = threadIdx.x;
    const int lane = tid & 31, wid = tid >> 5;
    const int qg   = wid & 7;            // q-row group
    const int half = wid >> 3;           // key half (0/1)
    const int g    = lane >> 2;
    const int u    = lane & 3;
    const int q0w  = qg * 16;
    const int b    = blockIdx.y;
    const int n0   = blockIdx.x * 128;

    {
        const uint4* Qhg = (const uint4*)(g_Qh + ((size_t)(b * HW + n0)) * 64);
        const uint4* Qlg = (const uint4*)(g_Ql + ((size_t)(b * HW + n0)) * 64);
        for (int e = tid; e < 1024; e += 512) {
            int r = e >> 3, c8 = e & 7;
            uint32_t o = SW128(r * 128 + c8 * 16);
            *(uint4*)(smem + OFF_QH + o) = Qhg[e];
            *(uint4*)(smem + OFF_QL + o) = Qlg[e];
        }
        const uint4* KHg = (const uint4*)(g_Kh + ((size_t)(b * HW)) * 64);
        const uint4* KLg = (const uint4*)(g_Kl + ((size_t)(b * HW)) * 64);
        for (int e = tid; e < 1024; e += 512) {
            int r = e >> 3, c8 = e & 7;
            uint32_t o = SW128(r * 128 + c8 * 16);
            *(uint4*)(smem + OFF_K + o)         = KHg[e];
            *(uint4*)(smem + OFF_K + 16384 + o) = KLg[e];
        }
        const __nv_bfloat16* Vg = g_Vb + (size_t)b * 64 * HW;
        for (int e = tid; e < 1024; e += 512) {
            int c = e >> 4, j8 = e & 15;
            uint4 val = *(const uint4*)(Vg + (size_t)c * HW + j8 * 8);
            *(uint4*)(smem + OFF_V + (j8 >> 3) * 8192 +
                      SW128(c * 128 + (j8 & 7) * 16)) = val;
        }
        if (tid < 128) *(float*)(smem + OFF_AW + tid * 4) = fabsf(g_w[b * HW + tid]);
    }
    __syncthreads();

    float o[8][4];
    #pragma unroll
    for (int ct = 0; ct < 8; ct++)
        o[ct][0] = o[ct][1] = o[ct][2] = o[ct][3] = 0.f;
    float mrow0 = -1e30f, mrow1 = -1e30f, den0 = 0.f, den1 = 0.f;

    const int qrow = q0w + (lane & 15);

    for (int t = 0; t < 32; t++) {
        const int buf = t & 1;

        if (t < 31) {
            const int m1 = (t + 1) * 128, nb = buf ^ 1;
            const uint4* KHg = (const uint4*)(g_Kh + ((size_t)(b * HW + m1)) * 64);
            const uint4* KLg = (const uint4*)(g_Kl + ((size_t)(b * HW + m1)) * 64);
            char* kb = smem + OFF_K + nb * 32768;
            for (int e = tid; e < 1024; e += 512) {
                int r = e >> 3, c8 = e & 7;
                uint32_t oo = SW128(r * 128 + c8 * 16);
                *(uint4*)(kb + oo)         = KHg[e];
                *(uint4*)(kb + 16384 + oo) = KLg[e];
            }
            const __nv_bfloat16* Vg = g_Vb + (size_t)b * 64 * HW + m1;
            char* vb = smem + OFF_V + nb * 16384;
            for (int e = tid; e < 1024; e += 512) {
                int c = e >> 4, j8 = e & 15;
                uint4 val = *(const uint4*)(Vg + (size_t)c * HW + j8 * 8);
                *(uint4*)(vb + (j8 >> 3) * 8192 +
                          SW128(c * 128 + (j8 & 7) * 16)) = val;
            }
            if (tid < 128)
                *(float*)(smem + OFF_AW + nb * 512 + tid * 4) =
                    fabsf(g_w[b * HW + m1 + tid]);
        }

        const uint32_t kh_b = sbase + OFF_K + buf * 32768;
        const uint32_t kl_b = kh_b + 16384;
        const float*   awp  = (const float*)(smem + OFF_AW + buf * 512);

        // ---- reload Q fragments for this tile (short live range) ----
        uint32_t qh[4][4], ql[4][4];
        #pragma unroll
        for (int ks = 0; ks < 4; ks++) {
            const uint32_t cb = ks * 32 + (lane >> 4) * 16;
            LDMX4(qh[ks], sbase + OFF_QH + SW128(qrow * 128 + cb));
            LDMX4(ql[ks], sbase + OFF_QL + SW128(qrow * 128 + cb));
        }

        // ---- S = QK^T for this warp's 64 keys, hi/lo 3-pass ----
        float s[8][4];
        #pragma unroll
        for (int i = 0; i < 8; i++)
            s[i][0] = s[i][1] = s[i][2] = s[i][3] = 0.f;

        #pragma unroll
        for (int i = 0; i < 8; i++) {
            const int nt = half * 8 + i;
            const uint32_t roff = (nt * 8 + (lane & 7)) * 128 + (lane >> 3) * 16;
            uint32_t bh[8], bl[8];
            LDMX4(bh,     kh_b + SW128(roff));
            LDMX4(bh + 4, kh_b + SW128(roff + 64));
            LDMX4(bl,     kl_b + SW128(roff));
            LDMX4(bl + 4, kl_b + SW128(roff + 64));
            #pragma unroll
            for (int ks = 0; ks < 4; ks++) {
                MMA16816(s[i], qh[ks], bh[2 * ks], bh[2 * ks + 1]);
                MMA16816(s[i], qh[ks], bl[2 * ks], bl[2 * ks + 1]);
                MMA16816(s[i], ql[ks], bh[2 * ks], bh[2 * ks + 1]);
            }
        }

        // ---- online softmax (quad-local, per-warp chain) ----
        float mx0 = s[0][0], mx1 = s[0][2];
        #pragma unroll
        for (int i = 0; i < 8; i++) {
            mx0 = fmaxf(mx0, fmaxf(s[i][0], s[i][1]));
            mx1 = fmaxf(mx1, fmaxf(s[i][2], s[i][3]));
        }
        mx0 = fmaxf(mx0, __shfl_xor_sync(0xffffffffu, mx0, 1));
        mx0 = fmaxf(mx0, __shfl_xor_sync(0xffffffffu, mx0, 2));
        mx1 = fmaxf(mx1, __shfl_xor_sync(0xffffffffu, mx1, 1));
        mx1 = fmaxf(mx1, __shfl_xor_sync(0xffffffffu, mx1, 2));

        const float mn0 = fmaxf(mrow0, mx0), mn1 = fmaxf(mrow1, mx1);
        const float cr0 = ex2f(mrow0 - mn0), cr1 = ex2f(mrow1 - mn1);
        mrow0 = mn0; mrow1 = mn1;

        float ws0 = 0.f, ws1 = 0.f;
        #pragma unroll
        for (int i = 0; i < 8; i++) {
            const float2 aw = *(const float2*)&awp[half * 64 + i * 8 + 2 * u];
            s[i][0] = ex2f(s[i][0] - mn0);
            s[i][1] = ex2f(s[i][1] - mn0);
            s[i][2] = ex2f(s[i][2] - mn1);
            s[i][3] = ex2f(s[i][3] - mn1);
            ws0 += s[i][0] * aw.x + s[i][1] * aw.y;
            ws1 += s[i][2] * aw.x + s[i][3] * aw.y;
        }
        ws0 += __shfl_xor_sync(0xffffffffu, ws0, 1);
        ws0 += __shfl_xor_sync(0xffffffffu, ws0, 2);
        ws1 += __shfl_xor_sync(0xffffffffu, ws1, 1);
        ws1 += __shfl_xor_sync(0xffffffffu, ws1, 2);
        den0 = den0 * cr0 + ws0;
        den1 = den1 * cr1 + ws1;

        #pragma unroll
        for (int ct = 0; ct < 8; ct++) {
            o[ct][0] *= cr0; o[ct][1] *= cr0;
            o[ct][2] *= cr1; o[ct][3] *= cr1;
        }

        uint32_t aP[4][4];
        #pragma unroll
        for (int j = 0; j < 4; j++) {
            aP[j][0] = bf16x2_pack(s[2 * j][0],     s[2 * j][1]);
            aP[j][1] = bf16x2_pack(s[2 * j][2],     s[2 * j][3]);
            aP[j][2] = bf16x2_pack(s[2 * j + 1][0], s[2 * j + 1][1]);
            aP[j][3] = bf16x2_pack(s[2 * j + 1][2], s[2 * j + 1][3]);
        }

        const uint32_t v_b = sbase + OFF_V + buf * 16384 + half * 8192;
        #pragma unroll
        for (int ct = 0; ct < 8; ct++) {
            const uint32_t roff = (ct * 8 + (lane & 7)) * 128 + (lane >> 3) * 16;
            uint32_t vb[8];
            LDMX4(vb,     v_b + SW128(roff));
            LDMX4(vb + 4, v_b + SW128(roff + 64));
            #pragma unroll
            for (int j = 0; j < 4; j++)
                MMA16816(o[ct], aP[j], vb[2 * j], vb[2 * j + 1]);
        }
        __syncthreads();
    }

    // ---- merge the two key-half chains, stage, write ----
    const int r0 = q0w + g, r1 = q0w + g + 8;
    float* msh = (float*)(smem + OFF_MSH);
    float* dsh = (float*)(smem + OFF_DSH);
    if (u == 0) {
        msh[half * 128 + r0] = mrow0;  msh[half * 128 + r1] = mrow1;
        dsh[half * 128 + r0] = den0;   dsh[half * 128 + r1] = den1;
    }
    __syncthreads();

    const float g0 = gamma[0];
    const float mo0 = msh[(1 - half) * 128 + r0], do0 = dsh[(1 - half) * 128 + r0];
    const float mo1 = msh[(1 - half) * 128 + r1], do1 = dsh[(1 - half) * 128 + r1];
    const float mf0 = fmaxf(mrow0, mo0), mf1 = fmaxf(mrow1, mo1);
    const float sm0 = ex2f(mrow0 - mf0), sm1 = ex2f(mrow1 - mf1);
    const float df0 = den0 * sm0 + do0 * ex2f(mo0 - mf0);
    const float df1 = den1 * sm1 + do1 * ex2f(mo1 - mf1);
    const float inv0 = g0 * sm0 / df0, inv1 = g0 * sm1 / df1;

    float* Ost = (float*)(smem + (half ? OFF_OST1 : OFF_OST0));   // [64c][128q]
    #pragma unroll
    for (int ct = 0; ct < 8; ct++) {
        const int c = ct * 8 + 2 * u;
        Ost[c * 128 + r0]       = o[ct][0] * inv0;
        Ost[(c + 1) * 128 + r0] = o[ct][1] * inv0;
        Ost[c * 128 + r1]       = o[ct][2] * inv1;
        Ost[(c + 1) * 128 + r1] = o[ct][3] * inv1;
    }
    __syncthreads();

    const float* O0 = (const float*)(smem + OFF_OST0);
    const float* O1 = (const float*)(smem + OFF_OST1);
    for (int e = tid; e < 2048; e += 512) {
        const int c = e >> 5, q4 = (e & 31) * 4;
        const int idx = c * 128 + q4;
        float4 a = *(const float4*)&O0[idx];
        const float4 bb = *(const float4*)&O1[idx];
        const size_t off = (size_t)(b * 64 + c) * HW + n0 + q4;
        const float4 xv = *(const float4*)&x[off];
        a.x += bb.x + xv.x; a.y += bb.y + xv.y;
        a.z += bb.z + xv.z; a.w += bb.w + xv.w;
        *(float4*)&out[off] = a;
    }
}

// ================= launch =================
extern "C" void kernel_launch(void* const* d_in, const int* in_sizes, int n_in,
                              void* d_out, int out_size)
{
    (void)in_sizes; (void)n_in; (void)out_size;
    const float* x       = (const float*)d_in[0];
    const float* Wq      = (const float*)d_in[1];
    const float* bq      = (const float*)d_in[2];
    const float* Wk      = (const float*)d_in[3];
    const float* bk      = (const float*)d_in[4];
    const float* Wv      = (const float*)d_in[5];
    const float* bv      = (const float*)d_in[6];
    const float* We1     = (const float*)d_in[7];
    const float* be1     = (const float*)d_in[8];
    const float* bn_w    = (const float*)d_in[9];
    const float* bn_b    = (const float*)d_in[10];
    const float* bn_mean = (const float*)d_in[11];
    const float* bn_var  = (const float*)d_in[12];
    const float* We2     = (const float*)d_in[13];
    const float* be2     = (const float*)d_in[14];
    const float* gamma   = (const float*)d_in[15];
    const float* beta    = (const float*)d_in[16];
    float* out = (float*)d_out;

    cudaFuncSetAttribute(edge_kernel, cudaFuncAttributeMaxDynamicSharedMemorySize,
                         EDGE_SMEM);
    edge_kernel<<<dim3(32, NB), 256, EDGE_SMEM>>>(x, We1, be1, bn_w, bn_b,
                                                  bn_mean, bn_var, We2, be2, beta);
    qkv_kernel<<<dim3(64, NB), 256>>>(x, Wq, bq, Wk, bk, Wv, bv);

    cudaFuncSetAttribute(flash_kernel, cudaFuncAttributeMaxDynamicSharedMemorySize,
                         SMEM_BYTES);
    flash_kernel<<<dim3(32, NB), 512, SMEM_BYTES>>>(x, gamma, out);
}

// round 10
// speedup vs baseline: 1.8760x; 1.2590x over previous
#include <cuda_runtime.h>
#include <cuda_fp16.h>
#include <cstdint>

#define HW    4096
#define NB    4
#define LOG2E 1.44269504088896340736f

// ---------------- scratch (device globals: allocation-free) ----------------
__device__ __half g_Qf[NB * HW * 64];   // [b][n][c] fp16, pre-scaled by log2e
__device__ __half g_Kf[NB * HW * 64];   // [b][n][c] fp16
__device__ __half g_Vf[NB * 64 * HW];   // [b][c][m] fp16 (w folded in)
__device__ float  g_w [NB * HW];        // w[m] = 1 + beta*edge

// ---------------- f32x2 packed-FMA helpers ----------------
__device__ __forceinline__ double dup2(float x) {
    double r; asm("mov.b64 %0, {%1,%1};" : "=d"(r) : "f"(x)); return r;
}
__device__ __forceinline__ void ffma2(double &d, double a, double b) {
    asm("fma.rn.f32x2 %0, %1, %2, %0;" : "+d"(d) : "d"(a), "d"(b));
}
__device__ __forceinline__ void unpack2(double v, float &lo, float &hi) {
    asm("mov.b64 {%0,%1}, %2;" : "=f"(lo), "=f"(hi) : "d"(v));
}
__device__ __forceinline__ float ex2f(float x) {
    float r; asm("ex2.approx.f32 %0, %1;" : "=f"(r) : "f"(x)); return r;
}
__device__ __forceinline__ uint32_t f16x2_pack(float lo, float hi) {
    uint32_t r; asm("cvt.rn.f16x2.f32 %0, %1, %2;" : "=r"(r) : "f"(hi), "f"(lo));
    return r;
}
__device__ __forceinline__ uint32_t smem_u32(const void* p) {
    uint32_t a;
    asm("{ .reg .u64 t; cvta.to.shared.u64 t, %1; cvt.u32.u64 %0, t; }"
        : "=r"(a) : "l"(p));
    return a;
}

#define SW128(o) ((o) ^ (((o) >> 3) & 0x70))

// ---------------- mma.sync / ldmatrix (fp16) ----------------
#define LDMX4(r, addr) \
    asm volatile("ldmatrix.sync.aligned.m8n8.x4.shared.b16 {%0,%1,%2,%3}, [%4];" \
        : "=r"((r)[0]), "=r"((r)[1]), "=r"((r)[2]), "=r"((r)[3]) : "r"(addr))

#define MMA16816(d, a, b0, b1) \
    asm volatile("mma.sync.aligned.m16n8k16.row.col.f32.f16.f16.f32 " \
        "{%0,%1,%2,%3},{%4,%5,%6,%7},{%8,%9},{%0,%1,%2,%3};" \
        : "+f"((d)[0]), "+f"((d)[1]), "+f"((d)[2]), "+f"((d)[3]) \
        : "r"((a)[0]), "r"((a)[1]), "r"((a)[2]), "r"((a)[3]), "r"(b0), "r"(b1))

// ================= kernel 1: edge detector -> g_w (R6 proven config) ======
#define XT_FLOATS (64 * 4 * 66)                 // 16896
#define WS_FLOATS (64 * 9 * 32)                 // 18432
#define RED_STRIDE 34
#define RED_FLOATS (128 * RED_STRIDE)           // 4352
#define EDGE_SMEM ((XT_FLOATS + WS_FLOATS + RED_FLOATS) * 4)   // 158720 B

__global__ __launch_bounds__(256) void edge_kernel(
    const float* __restrict__ x,  const float* __restrict__ We1,
    const float* __restrict__ be1,
    const float* __restrict__ bn_w, const float* __restrict__ bn_b,
    const float* __restrict__ bn_mean, const float* __restrict__ bn_var,
    const float* __restrict__ We2, const float* __restrict__ be2,
    const float* __restrict__ beta)
{
    extern __shared__ float es[];
    float* xt  = es;                         // [64ch][4r][66c]
    float* Wsh = es + XT_FLOATS;             // [(cc*9+k)*32 + ch]
    float* red = es + XT_FLOATS + WS_FLOATS; // [128px][34]
    __shared__ float s_sc[32], s_sh[32], s_w2[32];

    const int tid = threadIdx.x;
    const int b   = blockIdx.y;
    const int pr0 = blockIdx.x * 2;

    if (tid < 32) {
        float s = bn_w[tid] * rsqrtf(bn_var[tid] + 1e-5f);
        s_sc[tid] = s;
        s_sh[tid] = (be1[tid] - bn_mean[tid]) * s + bn_b[tid];
        s_w2[tid] = We2[tid];
    }

    for (int e = tid; e < WS_FLOATS; e += 256) {
        int ch = e & 31, rest = e >> 5;
        int k = rest % 9, cc = rest / 9;
        Wsh[e] = We1[(ch * 64 + cc) * 9 + k];
    }
    for (int e = tid; e < XT_FLOATS; e += 256) {
        int c66 = e % 66, rest = e / 66;
        int r = rest & 3, ch = rest >> 2;
        int ir = pr0 - 1 + r, ic = c66 - 1;
        float v = 0.f;
        if (ir >= 0 && ir < 64 && ic >= 0 && ic < 64)
            v = x[(size_t)(b * 64 + ch) * HW + ir * 64 + ic];
        xt[e] = v;
    }
    __syncthreads();

    const int px  = tid & 127;
    const int cu  = tid >> 7;
    const int pr  = px >> 6, col = px & 63;

    double acc2[16];
    #pragma unroll
    for (int i = 0; i < 16; i++) acc2[i] = 0.0;

    for (int ccl = 0; ccl < 32; ccl++) {
        const int cc = cu * 32 + ccl;
        const float* xb = &xt[(cc * 4 + pr) * 66 + col];
        float xv[9];
        #pragma unroll
        for (int ry = 0; ry < 3; ry++)
            #pragma unroll
            for (int rx = 0; rx < 3; rx++)
                xv[ry * 3 + rx] = xb[ry * 66 + rx];
        #pragma unroll
        for (int k = 0; k < 9; k++) {
            double dv = dup2(xv[k]);
            const double* wrow = (const double*)&Wsh[(cc * 9 + k) * 32];
            #pragma unroll
            for (int c2 = 0; c2 < 16; c2++) ffma2(acc2[c2], dv, wrow[c2]);
        }
    }

    if (cu == 1) {
        double* rp = (double*)&red[px * RED_STRIDE];
        #pragma unroll
        for (int i = 0; i < 16; i++) rp[i] = acc2[i];
    }
    __syncthreads();
    if (cu == 0) {
        const double* rp = (const double*)&red[px * RED_STRIDE];
        float e2 = be2[0];
        #pragma unroll
        for (int c2 = 0; c2 < 16; c2++) {
            float a0, a1, p0, p1;
            unpack2(acc2[c2], a0, a1);
            unpack2(rp[c2],   p0, p1);
            a0 += p0; a1 += p1;
            const int ch = c2 * 2;
            float r0 = fmaxf(a0 * s_sc[ch]     + s_sh[ch],     0.f);
            float r1 = fmaxf(a1 * s_sc[ch + 1] + s_sh[ch + 1], 0.f);
            e2 += s_w2[ch] * r0 + s_w2[ch + 1] * r1;
        }
        float sig = 1.f / (1.f + ex2f(-e2 * LOG2E));
        g_w[b * HW + pr0 * 64 + px] = 1.f + beta[0] * sig;
    }
}

// ================= kernel 2: QKV projections -> fp16 =================
__global__ __launch_bounds__(256) void qkv_kernel(
    const float* __restrict__ x,
    const float* __restrict__ Wq, const float* __restrict__ bq,
    const float* __restrict__ Wk, const float* __restrict__ bk,
    const float* __restrict__ Wv, const float* __restrict__ bv)
{
    __shared__ __align__(16) float xs[64 * 64];
    __shared__ __align__(16) float WTq[32 * 64];
    __shared__ __align__(16) float WTk[32 * 64];
    __shared__ __align__(16) float WTv[32 * 64];

    const int tid = threadIdx.x;
    const int b   = blockIdx.y;
    const int n0  = blockIdx.x * 64;

    for (int e = tid; e < 4096; e += 256) {
        int c = e >> 6, j = e & 63;
        xs[c * 64 + j] = x[(size_t)(b * 64 + c) * HW + n0 + j];
    }

    const int tn = tid & 15, to = tid >> 4;
    double aq[4][2], ak[4][2], av[4][2];
    #pragma unroll
    for (int i = 0; i < 4; i++) {
        aq[i][0] = aq[i][1] = 0.0; ak[i][0] = ak[i][1] = 0.0; av[i][0] = av[i][1] = 0.0;
    }

    for (int chunk = 0; chunk < 2; chunk++) {
        __syncthreads();
        for (int e = tid; e < 2048; e += 256) {
            int o = e & 63, c = e >> 6;
            WTq[c * 64 + o] = Wq[o * 64 + chunk * 32 + c];
            WTk[c * 64 + o] = Wk[o * 64 + chunk * 32 + c];
            WTv[c * 64 + o] = Wv[o * 64 + chunk * 32 + c];
        }
        __syncthreads();
        #pragma unroll 4
        for (int cc = 0; cc < 32; cc++) {
            const float4 xv = *(const float4*)&xs[(chunk * 32 + cc) * 64 + tn * 4];
            const double2 wq = *(const double2*)&WTq[cc * 64 + to * 4];
            const double2 wk = *(const double2*)&WTk[cc * 64 + to * 4];
            const double2 wv = *(const double2*)&WTv[cc * 64 + to * 4];
            double dn[4] = {dup2(xv.x), dup2(xv.y), dup2(xv.z), dup2(xv.w)};
            #pragma unroll
            for (int jn = 0; jn < 4; jn++) {
                ffma2(aq[jn][0], dn[jn], wq.x); ffma2(aq[jn][1], dn[jn], wq.y);
                ffma2(ak[jn][0], dn[jn], wk.x); ffma2(ak[jn][1], dn[jn], wk.y);
                ffma2(av[jn][0], dn[jn], wv.x); ffma2(av[jn][1], dn[jn], wv.y);
            }
        }
    }

    const int ob = to * 4;
    float bqv[4], bkv[4], bvv[4];
    #pragma unroll
    for (int io = 0; io < 4; io++) {
        bqv[io] = bq[ob + io]; bkv[io] = bk[ob + io]; bvv[io] = bv[ob + io];
    }
    #pragma unroll
    for (int jn = 0; jn < 4; jn++) {
        const int n = n0 + tn * 4 + jn;
        float qf[4], kf[4], vf[4];
        unpack2(aq[jn][0], qf[0], qf[1]); unpack2(aq[jn][1], qf[2], qf[3]);
        unpack2(ak[jn][0], kf[0], kf[1]); unpack2(ak[jn][1], kf[2], kf[3]);
        unpack2(av[jn][0], vf[0], vf[1]); unpack2(av[jn][1], vf[2], vf[3]);
        const float wnj = g_w[b * HW + n];
        __half qh[4], kh[4];
        #pragma unroll
        for (int io = 0; io < 4; io++) {
            qh[io] = __float2half((qf[io] + bqv[io]) * LOG2E);
            kh[io] = __float2half(kf[io] + bkv[io]);
            g_Vf[((size_t)(b * 64 + ob + io)) * HW + n] =
                __float2half((vf[io] + bvv[io]) * wnj);
        }
        const size_t base = ((size_t)(b * HW + n)) * 64 + ob;
        *(__half2*)&g_Qf[base]     = __half2(qh[0], qh[1]);
        *(__half2*)&g_Qf[base + 2] = __half2(qh[2], qh[3]);
        *(__half2*)&g_Kf[base]     = __half2(kh[0], kh[1]);
        *(__half2*)&g_Kf[base + 2] = __half2(kh[2], kh[3]);
    }
}

// ================= kernel 3: fp16 flash attention, 16 warps ==============
#define OFF_QF 0            // 16KB [128 tok][64c] fp16 SW128
#define OFF_K  16384        // 2 bufs * 16KB
#define OFF_V  49152        // 2 bufs * 16KB
#define OFF_AW 81920        // 2 bufs * 128 f32
#define SMEM_BYTES 82944
// epilogue overlay:
#define OFF_OST0 0
#define OFF_OST1 32768
#define OFF_MSH  65536
#define OFF_DSH  66560

__global__ __launch_bounds__(512, 1) void flash_kernel(
    const float* __restrict__ x, const float* __restrict__ gamma,
    float* __restrict__ out)
{
    extern __shared__ char smem[];
    const uint32_t sbase = smem_u32(smem);
    const int tid  = threadIdx.x;
    const int lane = tid & 31, wid = tid >> 5;
    const int qg   = wid & 7;            // q-row group
    const int half = wid >> 3;           // key half (0/1)
    const int g    = lane >> 2;
    const int u    = lane & 3;
    const int q0w  = qg * 16;
    const int b    = blockIdx.y;
    const int n0   = blockIdx.x * 128;

    {
        const uint4* Qg = (const uint4*)(g_Qf + ((size_t)(b * HW + n0)) * 64);
        const uint4* Kg = (const uint4*)(g_Kf + ((size_t)(b * HW)) * 64);
        for (int e = tid; e < 1024; e += 512) {
            int r = e >> 3, c8 = e & 7;
            uint32_t o = SW128(r * 128 + c8 * 16);
            *(uint4*)(smem + OFF_QF + o) = Qg[e];
            *(uint4*)(smem + OFF_K + o)  = Kg[e];
        }
        const __half* Vg = g_Vf + (size_t)b * 64 * HW;
        for (int e = tid; e < 1024; e += 512) {
            int c = e >> 4, j8 = e & 15;
            uint4 val = *(const uint4*)(Vg + (size_t)c * HW + j8 * 8);
            *(uint4*)(smem + OFF_V + (j8 >> 3) * 8192 +
                      SW128(c * 128 + (j8 & 7) * 16)) = val;
        }
        if (tid < 128) *(float*)(smem + OFF_AW + tid * 4) = fabsf(g_w[b * HW + tid]);
    }
    __syncthreads();

    float o[8][4];
    #pragma unroll
    for (int ct = 0; ct < 8; ct++)
        o[ct][0] = o[ct][1] = o[ct][2] = o[ct][3] = 0.f;
    float mrow0 = -1e30f, mrow1 = -1e30f, den0 = 0.f, den1 = 0.f;

    const int qrow = q0w + (lane & 15);

    for (int t = 0; t < 32; t++) {
        const int buf = t & 1;

        if (t < 31) {
            const int m1 = (t + 1) * 128, nb = buf ^ 1;
            const uint4* Kg = (const uint4*)(g_Kf + ((size_t)(b * HW + m1)) * 64);
            char* kb = smem + OFF_K + nb * 16384;
            for (int e = tid; e < 1024; e += 512) {
                int r = e >> 3, c8 = e & 7;
                *(uint4*)(kb + SW128(r * 128 + c8 * 16)) = Kg[e];
            }
            const __half* Vg = g_Vf + (size_t)b * 64 * HW + m1;
            char* vb = smem + OFF_V + nb * 16384;
            for (int e = tid; e < 1024; e += 512) {
                int c = e >> 4, j8 = e & 15;
                uint4 val = *(const uint4*)(Vg + (size_t)c * HW + j8 * 8);
                *(uint4*)(vb + (j8 >> 3) * 8192 +
                          SW128(c * 128 + (j8 & 7) * 16)) = val;
            }
            if (tid < 128)
                *(float*)(smem + OFF_AW + nb * 512 + tid * 4) =
                    fabsf(g_w[b * HW + m1 + tid]);
        }

        const uint32_t k_b  = sbase + OFF_K + buf * 16384;
        const float*   awp  = (const float*)(smem + OFF_AW + buf * 512);

        // ---- reload Q fragments (short live range, no spills) ----
        uint32_t qf[4][4];
        #pragma unroll
        for (int ks = 0; ks < 4; ks++) {
            const uint32_t cb = ks * 32 + (lane >> 4) * 16;
            LDMX4(qf[ks], sbase + OFF_QF + SW128(qrow * 128 + cb));
        }

        // ---- S = QK^T for this warp's 64 keys (single fp16 pass) ----
        float s[8][4];
        #pragma unroll
        for (int i = 0; i < 8; i++)
            s[i][0] = s[i][1] = s[i][2] = s[i][3] = 0.f;

        #pragma unroll
        for (int i = 0; i < 8; i++) {
            const int nt = half * 8 + i;
            const uint32_t roff = (nt * 8 + (lane & 7)) * 128 + (lane >> 3) * 16;
            uint32_t bh[8];
            LDMX4(bh,     k_b + SW128(roff));
            LDMX4(bh + 4, k_b + SW128(roff + 64));
            #pragma unroll
            for (int ks = 0; ks < 4; ks++)
                MMA16816(s[i], qf[ks], bh[2 * ks], bh[2 * ks + 1]);
        }

        // ---- online softmax (quad-local, per-warp chain) ----
        float mx0 = s[0][0], mx1 = s[0][2];
        #pragma unroll
        for (int i = 0; i < 8; i++) {
            mx0 = fmaxf(mx0, fmaxf(s[i][0], s[i][1]));
            mx1 = fmaxf(mx1, fmaxf(s[i][2], s[i][3]));
        }
        mx0 = fmaxf(mx0, __shfl_xor_sync(0xffffffffu, mx0, 1));
        mx0 = fmaxf(mx0, __shfl_xor_sync(0xffffffffu, mx0, 2));
        mx1 = fmaxf(mx1, __shfl_xor_sync(0xffffffffu, mx1, 1));
        mx1 = fmaxf(mx1, __shfl_xor_sync(0xffffffffu, mx1, 2));

        const float mn0 = fmaxf(mrow0, mx0), mn1 = fmaxf(mrow1, mx1);
        const float cr0 = ex2f(mrow0 - mn0), cr1 = ex2f(mrow1 - mn1);
        mrow0 = mn0; mrow1 = mn1;

        float ws0 = 0.f, ws1 = 0.f;
        #pragma unroll
        for (int i = 0; i < 8; i++) {
            const float2 aw = *(const float2*)&awp[half * 64 + i * 8 + 2 * u];
            s[i][0] = ex2f(s[i][0] - mn0);
            s[i][1] = ex2f(s[i][1] - mn0);
            s[i][2] = ex2f(s[i][2] - mn1);
            s[i][3] = ex2f(s[i][3] - mn1);
            ws0 += s[i][0] * aw.x + s[i][1] * aw.y;
            ws1 += s[i][2] * aw.x + s[i][3] * aw.y;
        }
        ws0 += __shfl_xor_sync(0xffffffffu, ws0, 1);
        ws0 += __shfl_xor_sync(0xffffffffu, ws0, 2);
        ws1 += __shfl_xor_sync(0xffffffffu, ws1, 1);
        ws1 += __shfl_xor_sync(0xffffffffu, ws1, 2);
        den0 = den0 * cr0 + ws0;
        den1 = den1 * cr1 + ws1;

        #pragma unroll
        for (int ct = 0; ct < 8; ct++) {
            o[ct][0] *= cr0; o[ct][1] *= cr0;
            o[ct][2] *= cr1; o[ct][3] *= cr1;
        }

        uint32_t aP[4][4];
        #pragma unroll
        for (int j = 0; j < 4; j++) {
            aP[j][0] = f16x2_pack(s[2 * j][0],     s[2 * j][1]);
            aP[j][1] = f16x2_pack(s[2 * j][2],     s[2 * j][3]);
            aP[j][2] = f16x2_pack(s[2 * j + 1][0], s[2 * j + 1][1]);
            aP[j][3] = f16x2_pack(s[2 * j + 1][2], s[2 * j + 1][3]);
        }

        const uint32_t v_b = sbase + OFF_V + buf * 16384 + half * 8192;
        #pragma unroll
        for (int ct = 0; ct < 8; ct++) {
            const uint32_t roff = (ct * 8 + (lane & 7)) * 128 + (lane >> 3) * 16;
            uint32_t vb[8];
            LDMX4(vb,     v_b + SW128(roff));
            LDMX4(vb + 4, v_b + SW128(roff + 64));
            #pragma unroll
            for (int j = 0; j < 4; j++)
                MMA16816(o[ct], aP[j], vb[2 * j], vb[2 * j + 1]);
        }
        __syncthreads();
    }

    // ---- merge the two key-half chains, stage, write ----
    const int r0 = q0w + g, r1 = q0w + g + 8;
    float* msh = (float*)(smem + OFF_MSH);
    float* dsh = (float*)(smem + OFF_DSH);
    if (u == 0) {
        msh[half * 128 + r0] = mrow0;  msh[half * 128 + r1] = mrow1;
        dsh[half * 128 + r0] = den0;   dsh[half * 128 + r1] = den1;
    }
    __syncthreads();

    const float g0 = gamma[0];
    const float mo0 = msh[(1 - half) * 128 + r0], do0 = dsh[(1 - half) * 128 + r0];
    const float mo1 = msh[(1 - half) * 128 + r1], do1 = dsh[(1 - half) * 128 + r1];
    const float mf0 = fmaxf(mrow0, mo0), mf1 = fmaxf(mrow1, mo1);
    const float sm0 = ex2f(mrow0 - mf0), sm1 = ex2f(mrow1 - mf1);
    const float df0 = den0 * sm0 + do0 * ex2f(mo0 - mf0);
    const float df1 = den1 * sm1 + do1 * ex2f(mo1 - mf1);
    const float inv0 = g0 * sm0 / df0, inv1 = g0 * sm1 / df1;

    float* Ost = (float*)(smem + (half ? OFF_OST1 : OFF_OST0));   // [64c][128q]
    #pragma unroll
    for (int ct = 0; ct < 8; ct++) {
        const int c = ct * 8 + 2 * u;
        Ost[c * 128 + r0]       = o[ct][0] * inv0;
        Ost[(c + 1) * 128 + r0] = o[ct][1] * inv0;
        Ost[c * 128 + r1]       = o[ct][2] * inv1;
        Ost[(c + 1) * 128 + r1] = o[ct][3] * inv1;
    }
    __syncthreads();

    const float* O0 = (const float*)(smem + OFF_OST0);
    const float* O1 = (const float*)(smem + OFF_OST1);
    for (int e = tid; e < 2048; e += 512) {
        const int c = e >> 5, q4 = (e & 31) * 4;
        const int idx = c * 128 + q4;
        float4 a = *(const float4*)&O0[idx];
        const float4 bb = *(const float4*)&O1[idx];
        const size_t off = (size_t)(b * 64 + c) * HW + n0 + q4;
        const float4 xv = *(const float4*)&x[off];
        a.x += bb.x + xv.x; a.y += bb.y + xv.y;
        a.z += bb.z + xv.z; a.w += bb.w + xv.w;
        *(float4*)&out[off] = a;
    }
}

// ================= launch =================
extern "C" void kernel_launch(void* const* d_in, const int* in_sizes, int n_in,
                              void* d_out, int out_size)
{
    (void)in_sizes; (void)n_in; (void)out_size;
    const float* x       = (const float*)d_in[0];
    const float* Wq      = (const float*)d_in[1];
    const float* bq      = (const float*)d_in[2];
    const float* Wk      = (const float*)d_in[3];
    const float* bk      = (const float*)d_in[4];
    const float* Wv      = (const float*)d_in[5];
    const float* bv      = (const float*)d_in[6];
    const float* We1     = (const float*)d_in[7];
    const float* be1     = (const float*)d_in[8];
    const float* bn_w    = (const float*)d_in[9];
    const float* bn_b    = (const float*)d_in[10];
    const float* bn_mean = (const float*)d_in[11];
    const float* bn_var  = (const float*)d_in[12];
    const float* We2     = (const float*)d_in[13];
    const float* be2     = (const float*)d_in[14];
    const float* gamma   = (const float*)d_in[15];
    const float* beta    = (const float*)d_in[16];
    float* out = (float*)d_out;

    cudaFuncSetAttribute(edge_kernel, cudaFuncAttributeMaxDynamicSharedMemorySize,
                         EDGE_SMEM);
    edge_kernel<<<dim3(32, NB), 256, EDGE_SMEM>>>(x, We1, be1, bn_w, bn_b,
                                                  bn_mean, bn_var, We2, be2, beta);
    qkv_kernel<<<dim3(64, NB), 256>>>(x, Wq, bq, Wk, bk, Wv, bv);

    cudaFuncSetAttribute(flash_kernel, cudaFuncAttributeMaxDynamicSharedMemorySize,
                         SMEM_BYTES);
    flash_kernel<<<dim3(32, NB), 512, SMEM_BYTES>>>(x, gamma, out);
}

// round 11
// speedup vs baseline: 1.9204x; 1.0237x over previous
#include <cuda_runtime.h>
#include <cuda_fp16.h>
#include <cstdint>

#define HW    4096
#define NB    4
#define LOG2E 1.44269504088896340736f

// ---------------- scratch (device globals: allocation-free) ----------------
__device__ __half g_Qf[NB * HW * 64];   // [b][n][c] fp16, pre-scaled by log2e
__device__ __half g_Kf[NB * HW * 64];   // [b][n][c] fp16
__device__ __half g_Vf[NB * 64 * HW];   // [b][c][m] fp16 (w folded in)
__device__ float  g_w [NB * HW];        // w[m] = 1 + beta*edge

// ---------------- f32x2 packed-FMA helpers ----------------
__device__ __forceinline__ double dup2(float x) {
    double r; asm("mov.b64 %0, {%1,%1};" : "=d"(r) : "f"(x)); return r;
}
__device__ __forceinline__ void ffma2(double &d, double a, double b) {
    asm("fma.rn.f32x2 %0, %1, %2, %0;" : "+d"(d) : "d"(a), "d"(b));
}
__device__ __forceinline__ void unpack2(double v, float &lo, float &hi) {
    asm("mov.b64 {%0,%1}, %2;" : "=f"(lo), "=f"(hi) : "d"(v));
}
__device__ __forceinline__ float ex2f(float x) {
    float r; asm("ex2.approx.f32 %0, %1;" : "=f"(r) : "f"(x)); return r;
}
__device__ __forceinline__ uint32_t f16x2_pack(float lo, float hi) {
    uint32_t r; asm("cvt.rn.f16x2.f32 %0, %1, %2;" : "=r"(r) : "f"(hi), "f"(lo));
    return r;
}
__device__ __forceinline__ uint32_t ex2_h2(uint32_t h2) {
    asm("ex2.approx.f16x2 %0, %0;" : "+r"(h2));
    return h2;
}
__device__ __forceinline__ uint32_t smem_u32(const void* p) {
    uint32_t a;
    asm("{ .reg .u64 t; cvta.to.shared.u64 t, %1; cvt.u32.u64 %0, t; }"
        : "=r"(a) : "l"(p));
    return a;
}

#define SW128(o) ((o) ^ (((o) >> 3) & 0x70))

// ---------------- mma.sync / ldmatrix (fp16) ----------------
#define LDMX4(r, addr) \
    asm volatile("ldmatrix.sync.aligned.m8n8.x4.shared.b16 {%0,%1,%2,%3}, [%4];" \
        : "=r"((r)[0]), "=r"((r)[1]), "=r"((r)[2]), "=r"((r)[3]) : "r"(addr))

#define MMA16816(d, a, b0, b1) \
    asm volatile("mma.sync.aligned.m16n8k16.row.col.f32.f16.f16.f32 " \
        "{%0,%1,%2,%3},{%4,%5,%6,%7},{%8,%9},{%0,%1,%2,%3};" \
        : "+f"((d)[0]), "+f"((d)[1]), "+f"((d)[2]), "+f"((d)[3]) \
        : "r"((a)[0]), "r"((a)[1]), "r"((a)[2]), "r"((a)[3]), "r"(b0), "r"(b1))

// ================= kernel 1: edge detector -> g_w =================
#define XT_FLOATS (64 * 4 * 66)                 // 16896
#define WS_FLOATS (64 * 9 * 32)                 // 18432
#define RED_STRIDE 34
#define RED_FLOATS (128 * RED_STRIDE)           // 4352
#define EDGE_SMEM ((XT_FLOATS + WS_FLOATS + RED_FLOATS) * 4)   // 158720 B

__global__ __launch_bounds__(256) void edge_kernel(
    const float* __restrict__ x,  const float* __restrict__ We1,
    const float* __restrict__ be1,
    const float* __restrict__ bn_w, const float* __restrict__ bn_b,
    const float* __restrict__ bn_mean, const float* __restrict__ bn_var,
    const float* __restrict__ We2, const float* __restrict__ be2,
    const float* __restrict__ beta)
{
    extern __shared__ float es[];
    float* xt  = es;                         // [64ch][4r][66c]
    float* Wsh = es + XT_FLOATS;             // [(cc*9+k)*32 + ch]
    float* red = es + XT_FLOATS + WS_FLOATS; // [128px][34]
    __shared__ float s_sc[32], s_sh[32], s_w2[32];

    const int tid = threadIdx.x;
    const int b   = blockIdx.y;
    const int pr0 = blockIdx.x * 2;

    if (tid < 32) {
        float s = bn_w[tid] * rsqrtf(bn_var[tid] + 1e-5f);
        s_sc[tid] = s;
        s_sh[tid] = (be1[tid] - bn_mean[tid]) * s + bn_b[tid];
        s_w2[tid] = We2[tid];
    }

    for (int e = tid; e < WS_FLOATS; e += 256) {
        int ch = e & 31, rest = e >> 5;
        int k = rest % 9, cc = rest / 9;
        Wsh[e] = We1[(ch * 64 + cc) * 9 + k];
    }
    for (int e = tid; e < XT_FLOATS; e += 256) {
        int c66 = e % 66, rest = e / 66;
        int r = rest & 3, ch = rest >> 2;
        int ir = pr0 - 1 + r, ic = c66 - 1;
        float v = 0.f;
        if (ir >= 0 && ir < 64 && ic >= 0 && ic < 64)
            v = x[(size_t)(b * 64 + ch) * HW + ir * 64 + ic];
        xt[e] = v;
    }
    __syncthreads();

    const int px  = tid & 127;
    const int cu  = tid >> 7;
    const int pr  = px >> 6, col = px & 63;

    double acc2[16];
    #pragma unroll
    for (int i = 0; i < 16; i++) acc2[i] = 0.0;

    for (int ccl = 0; ccl < 32; ccl++) {
        const int cc = cu * 32 + ccl;
        const float* xb = &xt[(cc * 4 + pr) * 66 + col];
        float xv[9];
        #pragma unroll
        for (int ry = 0; ry < 3; ry++)
            #pragma unroll
            for (int rx = 0; rx < 3; rx++)
                xv[ry * 3 + rx] = xb[ry * 66 + rx];
        #pragma unroll
        for (int k = 0; k < 9; k++) {
            double dv = dup2(xv[k]);
            const double2* wrow = (const double2*)&Wsh[(cc * 9 + k) * 32];
            #pragma unroll
            for (int c4 = 0; c4 < 8; c4++) {
                const double2 w2 = wrow[c4];           // guaranteed LDS.128
                ffma2(acc2[2 * c4],     dv, w2.x);
                ffma2(acc2[2 * c4 + 1], dv, w2.y);
            }
        }
    }

    if (cu == 1) {
        double* rp = (double*)&red[px * RED_STRIDE];
        #pragma unroll
        for (int i = 0; i < 16; i++) rp[i] = acc2[i];
    }
    __syncthreads();
    if (cu == 0) {
        const double* rp = (const double*)&red[px * RED_STRIDE];
        float e2 = be2[0];
        #pragma unroll
        for (int c2 = 0; c2 < 16; c2++) {
            float a0, a1, p0, p1;
            unpack2(acc2[c2], a0, a1);
            unpack2(rp[c2],   p0, p1);
            a0 += p0; a1 += p1;
            const int ch = c2 * 2;
            float r0 = fmaxf(a0 * s_sc[ch]     + s_sh[ch],     0.f);
            float r1 = fmaxf(a1 * s_sc[ch + 1] + s_sh[ch + 1], 0.f);
            e2 += s_w2[ch] * r0 + s_w2[ch + 1] * r1;
        }
        float sig = 1.f / (1.f + ex2f(-e2 * LOG2E));
        g_w[b * HW + pr0 * 64 + px] = 1.f + beta[0] * sig;
    }
}

// ================= kernel 2: QKV projections -> fp16 =================
__global__ __launch_bounds__(256) void qkv_kernel(
    const float* __restrict__ x,
    const float* __restrict__ Wq, const float* __restrict__ bq,
    const float* __restrict__ Wk, const float* __restrict__ bk,
    const float* __restrict__ Wv, const float* __restrict__ bv)
{
    __shared__ __align__(16) float xs[64 * 64];
    __shared__ __align__(16) float WTq[32 * 64];
    __shared__ __align__(16) float WTk[32 * 64];
    __shared__ __align__(16) float WTv[32 * 64];

    const int tid = threadIdx.x;
    const int b   = blockIdx.y;
    const int n0  = blockIdx.x * 64;

    for (int e = tid; e < 4096; e += 256) {
        int c = e >> 6, j = e & 63;
        xs[c * 64 + j] = x[(size_t)(b * 64 + c) * HW + n0 + j];
    }

    const int tn = tid & 15, to = tid >> 4;
    double aq[4][2], ak[4][2], av[4][2];
    #pragma unroll
    for (int i = 0; i < 4; i++) {
        aq[i][0] = aq[i][1] = 0.0; ak[i][0] = ak[i][1] = 0.0; av[i][0] = av[i][1] = 0.0;
    }

    for (int chunk = 0; chunk < 2; chunk++) {
        __syncthreads();
        for (int e = tid; e < 2048; e += 256) {
            int o = e & 63, c = e >> 6;
            WTq[c * 64 + o] = Wq[o * 64 + chunk * 32 + c];
            WTk[c * 64 + o] = Wk[o * 64 + chunk * 32 + c];
            WTv[c * 64 + o] = Wv[o * 64 + chunk * 32 + c];
        }
        __syncthreads();
        #pragma unroll 4
        for (int cc = 0; cc < 32; cc++) {
            const float4 xv = *(const float4*)&xs[(chunk * 32 + cc) * 64 + tn * 4];
            const double2 wq = *(const double2*)&WTq[cc * 64 + to * 4];
            const double2 wk = *(const double2*)&WTk[cc * 64 + to * 4];
            const double2 wv = *(const double2*)&WTv[cc * 64 + to * 4];
            double dn[4] = {dup2(xv.x), dup2(xv.y), dup2(xv.z), dup2(xv.w)};
            #pragma unroll
            for (int jn = 0; jn < 4; jn++) {
                ffma2(aq[jn][0], dn[jn], wq.x); ffma2(aq[jn][1], dn[jn], wq.y);
                ffma2(ak[jn][0], dn[jn], wk.x); ffma2(ak[jn][1], dn[jn], wk.y);
                ffma2(av[jn][0], dn[jn], wv.x); ffma2(av[jn][1], dn[jn], wv.y);
            }
        }
    }

    const int ob = to * 4;
    float bqv[4], bkv[4], bvv[4];
    #pragma unroll
    for (int io = 0; io < 4; io++) {
        bqv[io] = bq[ob + io]; bkv[io] = bk[ob + io]; bvv[io] = bv[ob + io];
    }
    #pragma unroll
    for (int jn = 0; jn < 4; jn++) {
        const int n = n0 + tn * 4 + jn;
        float qf[4], kf[4], vf[4];
        unpack2(aq[jn][0], qf[0], qf[1]); unpack2(aq[jn][1], qf[2], qf[3]);
        unpack2(ak[jn][0], kf[0], kf[1]); unpack2(ak[jn][1], kf[2], kf[3]);
        unpack2(av[jn][0], vf[0], vf[1]); unpack2(av[jn][1], vf[2], vf[3]);
        const float wnj = g_w[b * HW + n];
        __half qh[4], kh[4];
        #pragma unroll
        for (int io = 0; io < 4; io++) {
            qh[io] = __float2half((qf[io] + bqv[io]) * LOG2E);
            kh[io] = __float2half(kf[io] + bkv[io]);
            g_Vf[((size_t)(b * 64 + ob + io)) * HW + n] =
                __float2half((vf[io] + bvv[io]) * wnj);
        }
        const size_t base = ((size_t)(b * HW + n)) * 64 + ob;
        *(__half2*)&g_Qf[base]     = __half2(qh[0], qh[1]);
        *(__half2*)&g_Qf[base + 2] = __half2(qh[2], qh[3]);
        *(__half2*)&g_Kf[base]     = __half2(kh[0], kh[1]);
        *(__half2*)&g_Kf[base + 2] = __half2(kh[2], kh[3]);
    }
}

// ================= kernel 3: fp16 flash attention, 16 warps ==============
#define OFF_QF 0            // 16KB [128 tok][64c] fp16 SW128
#define OFF_K  16384        // 2 bufs * 16KB
#define OFF_V  49152        // 2 bufs * 16KB
#define OFF_AW 81920        // 2 bufs * 128 f32
#define SMEM_BYTES 82944
// epilogue overlay:
#define OFF_OST0 0
#define OFF_OST1 32768
#define OFF_MSH  65536
#define OFF_DSH  66560

__global__ __launch_bounds__(512, 1) void flash_kernel(
    const float* __restrict__ x, const float* __restrict__ gamma,
    float* __restrict__ out)
{
    extern __shared__ char smem[];
    const uint32_t sbase = smem_u32(smem);
    const int tid  = threadIdx.x;
    const int lane = tid & 31, wid = tid >> 5;
    const int qg   = wid & 7;            // q-row group
    const int half = wid >> 3;           // key half (0/1)
    const int g    = lane >> 2;
    const int u    = lane & 3;
    const int q0w  = qg * 16;
    const int b    = blockIdx.y;
    const int n0   = blockIdx.x * 128;

    {
        const uint4* Qg = (const uint4*)(g_Qf + ((size_t)(b * HW + n0)) * 64);
        const uint4* Kg = (const uint4*)(g_Kf + ((size_t)(b * HW)) * 64);
        for (int e = tid; e < 1024; e += 512) {
            int r = e >> 3, c8 = e & 7;
            uint32_t o = SW128(r * 128 + c8 * 16);
            *(uint4*)(smem + OFF_QF + o) = Qg[e];
            *(uint4*)(smem + OFF_K + o)  = Kg[e];
        }
        const __half* Vg = g_Vf + (size_t)b * 64 * HW;
        for (int e = tid; e < 1024; e += 512) {
            int c = e >> 4, j8 = e & 15;
            uint4 val = *(const uint4*)(Vg + (size_t)c * HW + j8 * 8);
            *(uint4*)(smem + OFF_V + (j8 >> 3) * 8192 +
                      SW128(c * 128 + (j8 & 7) * 16)) = val;
        }
        if (tid < 128) *(float*)(smem + OFF_AW + tid * 4) = fabsf(g_w[b * HW + tid]);
    }
    __syncthreads();

    float o[8][4];
    #pragma unroll
    for (int ct = 0; ct < 8; ct++)
        o[ct][0] = o[ct][1] = o[ct][2] = o[ct][3] = 0.f;
    float mrow0 = -1e30f, mrow1 = -1e30f, den0 = 0.f, den1 = 0.f;

    const int qrow = q0w + (lane & 15);

    for (int t = 0; t < 32; t++) {
        const int buf = t & 1;

        if (t < 31) {
            const int m1 = (t + 1) * 128, nb = buf ^ 1;
            const uint4* Kg = (const uint4*)(g_Kf + ((size_t)(b * HW + m1)) * 64);
            char* kb = smem + OFF_K + nb * 16384;
            for (int e = tid; e < 1024; e += 512) {
                int r = e >> 3, c8 = e & 7;
                *(uint4*)(kb + SW128(r * 128 + c8 * 16)) = Kg[e];
            }
            const __half* Vg = g_Vf + (size_t)b * 64 * HW + m1;
            char* vb = smem + OFF_V + nb * 16384;
            for (int e = tid; e < 1024; e += 512) {
                int c = e >> 4, j8 = e & 15;
                uint4 val = *(const uint4*)(Vg + (size_t)c * HW + j8 * 8);
                *(uint4*)(vb + (j8 >> 3) * 8192 +
                          SW128(c * 128 + (j8 & 7) * 16)) = val;
            }
            if (tid < 128)
                *(float*)(smem + OFF_AW + nb * 512 + tid * 4) =
                    fabsf(g_w[b * HW + m1 + tid]);
        }

        const uint32_t k_b  = sbase + OFF_K + buf * 16384;
        const float*   awp  = (const float*)(smem + OFF_AW + buf * 512);

        // ---- reload Q fragments (short live range, no spills) ----
        uint32_t qf[4][4];
        #pragma unroll
        for (int ks = 0; ks < 4; ks++) {
            const uint32_t cb = ks * 32 + (lane >> 4) * 16;
            LDMX4(qf[ks], sbase + OFF_QF + SW128(qrow * 128 + cb));
        }

        // ---- S = QK^T for this warp's 64 keys (single fp16 pass) ----
        float s[8][4];
        #pragma unroll
        for (int i = 0; i < 8; i++)
            s[i][0] = s[i][1] = s[i][2] = s[i][3] = 0.f;

        #pragma unroll
        for (int i = 0; i < 8; i++) {
            const int nt = half * 8 + i;
            const uint32_t roff = (nt * 8 + (lane & 7)) * 128 + (lane >> 3) * 16;
            uint32_t bh[8];
            LDMX4(bh,     k_b + SW128(roff));
            LDMX4(bh + 4, k_b + SW128(roff + 64));
            #pragma unroll
            for (int ks = 0; ks < 4; ks++)
                MMA16816(s[i], qf[ks], bh[2 * ks], bh[2 * ks + 1]);
        }

        // ---- online softmax (quad-local, per-warp chain) ----
        float mx0 = s[0][0], mx1 = s[0][2];
        #pragma unroll
        for (int i = 0; i < 8; i++) {
            mx0 = fmaxf(mx0, fmaxf(s[i][0], s[i][1]));
            mx1 = fmaxf(mx1, fmaxf(s[i][2], s[i][3]));
        }
        mx0 = fmaxf(mx0, __shfl_xor_sync(0xffffffffu, mx0, 1));
        mx0 = fmaxf(mx0, __shfl_xor_sync(0xffffffffu, mx0, 2));
        mx1 = fmaxf(mx1, __shfl_xor_sync(0xffffffffu, mx1, 1));
        mx1 = fmaxf(mx1, __shfl_xor_sync(0xffffffffu, mx1, 2));

        const float mn0 = fmaxf(mrow0, mx0), mn1 = fmaxf(mrow1, mx1);
        const float cr0 = ex2f(mrow0 - mn0), cr1 = ex2f(mrow1 - mn1);
        mrow0 = mn0; mrow1 = mn1;

        // ---- p = exp2(s - mn) via f16x2 MUFU (output IS the A-fragment) ----
        float ws0 = 0.f, ws1 = 0.f;
        uint32_t aP[4][4];
        #pragma unroll
        for (int i = 0; i < 8; i++) {
            const float2 aw = *(const float2*)&awp[half * 64 + i * 8 + 2 * u];
            uint32_t h01 = ex2_h2(f16x2_pack(s[i][0] - mn0, s[i][1] - mn0));
            uint32_t h23 = ex2_h2(f16x2_pack(s[i][2] - mn1, s[i][3] - mn1));
            aP[i >> 1][(i & 1) * 2]     = h01;
            aP[i >> 1][(i & 1) * 2 + 1] = h23;
            const float2 p01 = __half22float2(*(const __half2*)&h01);
            const float2 p23 = __half22float2(*(const __half2*)&h23);
            ws0 += p01.x * aw.x + p01.y * aw.y;
            ws1 += p23.x * aw.x + p23.y * aw.y;
        }
        ws0 += __shfl_xor_sync(0xffffffffu, ws0, 1);
        ws0 += __shfl_xor_sync(0xffffffffu, ws0, 2);
        ws1 += __shfl_xor_sync(0xffffffffu, ws1, 1);
        ws1 += __shfl_xor_sync(0xffffffffu, ws1, 2);
        den0 = den0 * cr0 + ws0;
        den1 = den1 * cr1 + ws1;

        #pragma unroll
        for (int ct = 0; ct < 8; ct++) {
            o[ct][0] *= cr0; o[ct][1] *= cr0;
            o[ct][2] *= cr1; o[ct][3] *= cr1;
        }

        const uint32_t v_b = sbase + OFF_V + buf * 16384 + half * 8192;
        #pragma unroll
        for (int ct = 0; ct < 8; ct++) {
            const uint32_t roff = (ct * 8 + (lane & 7)) * 128 + (lane >> 3) * 16;
            uint32_t vb[8];
            LDMX4(vb,     v_b + SW128(roff));
            LDMX4(vb + 4, v_b + SW128(roff + 64));
            #pragma unroll
            for (int j = 0; j < 4; j++)
                MMA16816(o[ct], aP[j], vb[2 * j], vb[2 * j + 1]);
        }
        __syncthreads();
    }

    // ---- merge the two key-half chains, stage, write ----
    const int r0 = q0w + g, r1 = q0w + g + 8;
    float* msh = (float*)(smem + OFF_MSH);
    float* dsh = (float*)(smem + OFF_DSH);
    if (u == 0) {
        msh[half * 128 + r0] = mrow0;  msh[half * 128 + r1] = mrow1;
        dsh[half * 128 + r0] = den0;   dsh[half * 128 + r1] = den1;
    }
    __syncthreads();

    const float g0 = gamma[0];
    const float mo0 = msh[(1 - half) * 128 + r0], do0 = dsh[(1 - half) * 128 + r0];
    const float mo1 = msh[(1 - half) * 128 + r1], do1 = dsh[(1 - half) * 128 + r1];
    const float mf0 = fmaxf(mrow0, mo0), mf1 = fmaxf(mrow1, mo1);
    const float sm0 = ex2f(mrow0 - mf0), sm1 = ex2f(mrow1 - mf1);
    const float df0 = den0 * sm0 + do0 * ex2f(mo0 - mf0);
    const float df1 = den1 * sm1 + do1 * ex2f(mo1 - mf1);
    const float inv0 = g0 * sm0 / df0, inv1 = g0 * sm1 / df1;

    float* Ost = (float*)(smem + (half ? OFF_OST1 : OFF_OST0));   // [64c][128q]
    #pragma unroll
    for (int ct = 0; ct < 8; ct++) {
        const int c = ct * 8 + 2 * u;
        Ost[c * 128 + r0]       = o[ct][0] * inv0;
        Ost[(c + 1) * 128 + r0] = o[ct][1] * inv0;
        Ost[c * 128 + r1]       = o[ct][2] * inv1;
        Ost[(c + 1) * 128 + r1] = o[ct][3] * inv1;
    }
    __syncthreads();

    const float* O0 = (const float*)(smem + OFF_OST0);
    const float* O1 = (const float*)(smem + OFF_OST1);
    for (int e = tid; e < 2048; e += 512) {
        const int c = e >> 5, q4 = (e & 31) * 4;
        const int idx = c * 128 + q4;
        float4 a = *(const float4*)&O0[idx];
        const float4 bb = *(const float4*)&O1[idx];
        const size_t off = (size_t)(b * 64 + c) * HW + n0 + q4;
        const float4 xv = *(const float4*)&x[off];
        a.x += bb.x + xv.x; a.y += bb.y + xv.y;
        a.z += bb.z + xv.z; a.w += bb.w + xv.w;
        *(float4*)&out[off] = a;
    }
}

// ================= launch =================
extern "C" void kernel_launch(void* const* d_in, const int* in_sizes, int n_in,
                              void* d_out, int out_size)
{
    (void)in_sizes; (void)n_in; (void)out_size;
    const float* x       = (const float*)d_in[0];
    const float* Wq      = (const float*)d_in[1];
    const float* bq      = (const float*)d_in[2];
    const float* Wk      = (const float*)d_in[3];
    const float* bk      = (const float*)d_in[4];
    const float* Wv      = (const float*)d_in[5];
    const float* bv      = (const float*)d_in[6];
    const float* We1     = (const float*)d_in[7];
    const float* be1     = (const float*)d_in[8];
    const float* bn_w    = (const float*)d_in[9];
    const float* bn_b    = (const float*)d_in[10];
    const float* bn_mean = (const float*)d_in[11];
    const float* bn_var  = (const float*)d_in[12];
    const float* We2     = (const float*)d_in[13];
    const float* be2     = (const float*)d_in[14];
    const float* gamma   = (const float*)d_in[15];
    const float* beta    = (const float*)d_in[16];
    float* out = (float*)d_out;

    cudaFuncSetAttribute(edge_kernel, cudaFuncAttributeMaxDynamicSharedMemorySize,
                         EDGE_SMEM);
    edge_kernel<<<dim3(32, NB), 256, EDGE_SMEM>>>(x, We1, be1, bn_w, bn_b,
                                                  bn_mean, bn_var, We2, be2, beta);
    qkv_kernel<<<dim3(64, NB), 256>>>(x, Wq, bq, Wk, bk, Wv, bv);

    cudaFuncSetAttribute(flash_kernel, cudaFuncAttributeMaxDynamicSharedMemorySize,
                         SMEM_BYTES);
    flash_kernel<<<dim3(32, NB), 512, SMEM_BYTES>>>(x, gamma, out);
}

// round 12
// speedup vs baseline: 2.2854x; 1.1901x over previous
#include <cuda_runtime.h>
#include <cuda_fp16.h>
#include <cstdint>

#define HW    4096
#define NB    4
#define LOG2E 1.44269504088896340736f

// ---------------- scratch (device globals: allocation-free) ----------------
__device__ __half g_Qf[NB * HW * 64];   // [b][n][c] fp16, pre-scaled by log2e
__device__ __half g_Kf[NB * HW * 64];   // [b][n][c] fp16
__device__ __half g_Vf[NB * 64 * HW];   // [b][c][m] fp16 (w folded in)
__device__ float  g_w [NB * HW];        // w[m] = 1 + beta*edge

// ---------------- f32x2 packed-FMA helpers ----------------
__device__ __forceinline__ double dup2(float x) {
    double r; asm("mov.b64 %0, {%1,%1};" : "=d"(r) : "f"(x)); return r;
}
__device__ __forceinline__ void ffma2(double &d, double a, double b) {
    asm("fma.rn.f32x2 %0, %1, %2, %0;" : "+d"(d) : "d"(a), "d"(b));
}
__device__ __forceinline__ void unpack2(double v, float &lo, float &hi) {
    asm("mov.b64 {%0,%1}, %2;" : "=f"(lo), "=f"(hi) : "d"(v));
}
__device__ __forceinline__ float ex2f(float x) {
    float r; asm("ex2.approx.f32 %0, %1;" : "=f"(r) : "f"(x)); return r;
}
__device__ __forceinline__ uint32_t f16x2_pack(float lo, float hi) {
    uint32_t r; asm("cvt.rn.f16x2.f32 %0, %1, %2;" : "=r"(r) : "f"(hi), "f"(lo));
    return r;
}
__device__ __forceinline__ uint32_t ex2_h2(uint32_t h2) {
    asm("ex2.approx.f16x2 %0, %0;" : "+r"(h2));
    return h2;
}
__device__ __forceinline__ uint32_t movm_trans(uint32_t a) {
    uint32_t d;
    asm("movmatrix.sync.aligned.m8n8.trans.b16 %0, %1;" : "=r"(d) : "r"(a));
    return d;
}
__device__ __forceinline__ uint32_t smem_u32(const void* p) {
    uint32_t a;
    asm("{ .reg .u64 t; cvta.to.shared.u64 t, %1; cvt.u32.u64 %0, t; }"
        : "=r"(a) : "l"(p));
    return a;
}

#define SW128(o) ((o) ^ (((o) >> 3) & 0x70))
#define SWX(o)   ((o) ^ (((o) >> 4) & 0x70))   // for 256-byte rows

// ---------------- mma.sync / ldmatrix (fp16) ----------------
#define LDMX4(r, addr) \
    asm volatile("ldmatrix.sync.aligned.m8n8.x4.shared.b16 {%0,%1,%2,%3}, [%4];" \
        : "=r"((r)[0]), "=r"((r)[1]), "=r"((r)[2]), "=r"((r)[3]) : "r"(addr))

#define LDMX4T(r, addr) \
    asm volatile("ldmatrix.sync.aligned.m8n8.x4.trans.shared.b16 {%0,%1,%2,%3}, [%4];" \
        : "=r"((r)[0]), "=r"((r)[1]), "=r"((r)[2]), "=r"((r)[3]) : "r"(addr))

#define MMA16816(d, a, b0, b1) \
    asm volatile("mma.sync.aligned.m16n8k16.row.col.f32.f16.f16.f32 " \
        "{%0,%1,%2,%3},{%4,%5,%6,%7},{%8,%9},{%0,%1,%2,%3};" \
        : "+f"((d)[0]), "+f"((d)[1]), "+f"((d)[2]), "+f"((d)[3]) \
        : "r"((a)[0]), "r"((a)[1]), "r"((a)[2]), "r"((a)[3]), "r"(b0), "r"(b1))

// ================= kernel 1: edge detector -> g_w (R11 proven) ============
#define XT_FLOATS (64 * 4 * 66)
#define WS_FLOATS (64 * 9 * 32)
#define RED_STRIDE 34
#define RED_FLOATS (128 * RED_STRIDE)
#define EDGE_SMEM ((XT_FLOATS + WS_FLOATS + RED_FLOATS) * 4)

__global__ __launch_bounds__(256) void edge_kernel(
    const float* __restrict__ x,  const float* __restrict__ We1,
    const float* __restrict__ be1,
    const float* __restrict__ bn_w, const float* __restrict__ bn_b,
    const float* __restrict__ bn_mean, const float* __restrict__ bn_var,
    const float* __restrict__ We2, const float* __restrict__ be2,
    const float* __restrict__ beta)
{
    extern __shared__ float es[];
    float* xt  = es;
    float* Wsh = es + XT_FLOATS;
    float* red = es + XT_FLOATS + WS_FLOATS;
    __shared__ float s_sc[32], s_sh[32], s_w2[32];

    const int tid = threadIdx.x;
    const int b   = blockIdx.y;
    const int pr0 = blockIdx.x * 2;

    if (tid < 32) {
        float s = bn_w[tid] * rsqrtf(bn_var[tid] + 1e-5f);
        s_sc[tid] = s;
        s_sh[tid] = (be1[tid] - bn_mean[tid]) * s + bn_b[tid];
        s_w2[tid] = We2[tid];
    }

    for (int e = tid; e < WS_FLOATS; e += 256) {
        int ch = e & 31, rest = e >> 5;
        int k = rest % 9, cc = rest / 9;
        Wsh[e] = We1[(ch * 64 + cc) * 9 + k];
    }
    for (int e = tid; e < XT_FLOATS; e += 256) {
        int c66 = e % 66, rest = e / 66;
        int r = rest & 3, ch = rest >> 2;
        int ir = pr0 - 1 + r, ic = c66 - 1;
        float v = 0.f;
        if (ir >= 0 && ir < 64 && ic >= 0 && ic < 64)
            v = x[(size_t)(b * 64 + ch) * HW + ir * 64 + ic];
        xt[e] = v;
    }
    __syncthreads();

    const int px  = tid & 127;
    const int cu  = tid >> 7;
    const int pr  = px >> 6, col = px & 63;

    double acc2[16];
    #pragma unroll
    for (int i = 0; i < 16; i++) acc2[i] = 0.0;

    for (int ccl = 0; ccl < 32; ccl++) {
        const int cc = cu * 32 + ccl;
        const float* xb = &xt[(cc * 4 + pr) * 66 + col];
        float xv[9];
        #pragma unroll
        for (int ry = 0; ry < 3; ry++)
            #pragma unroll
            for (int rx = 0; rx < 3; rx++)
                xv[ry * 3 + rx] = xb[ry * 66 + rx];
        #pragma unroll
        for (int k = 0; k < 9; k++) {
            double dv = dup2(xv[k]);
            const double2* wrow = (const double2*)&Wsh[(cc * 9 + k) * 32];
            #pragma unroll
            for (int c4 = 0; c4 < 8; c4++) {
                const double2 w2 = wrow[c4];
                ffma2(acc2[2 * c4],     dv, w2.x);
                ffma2(acc2[2 * c4 + 1], dv, w2.y);
            }
        }
    }

    if (cu == 1) {
        double* rp = (double*)&red[px * RED_STRIDE];
        #pragma unroll
        for (int i = 0; i < 16; i++) rp[i] = acc2[i];
    }
    __syncthreads();
    if (cu == 0) {
        const double* rp = (const double*)&red[px * RED_STRIDE];
        float e2 = be2[0];
        #pragma unroll
        for (int c2 = 0; c2 < 16; c2++) {
            float a0, a1, p0, p1;
            unpack2(acc2[c2], a0, a1);
            unpack2(rp[c2],   p0, p1);
            a0 += p0; a1 += p1;
            const int ch = c2 * 2;
            float r0 = fmaxf(a0 * s_sc[ch]     + s_sh[ch],     0.f);
            float r1 = fmaxf(a1 * s_sc[ch + 1] + s_sh[ch + 1], 0.f);
            e2 += s_w2[ch] * r0 + s_w2[ch + 1] * r1;
        }
        float sig = 1.f / (1.f + ex2f(-e2 * LOG2E));
        g_w[b * HW + pr0 * 64 + px] = 1.f + beta[0] * sig;
    }
}

// ================= kernel 2: QKV via HMMA =================
// A = [Wq*log2e; Wk; Wv] (192 oc x 64 ic) fp16, B = x tile (64 ic x 128 tok)
// k-major via ldmatrix.trans. 12 warps: warp = one m16 tile. Q/K outputs
// transposed in-register via movmatrix -> [n][c] global; V natural [c][n].
__global__ __launch_bounds__(384) void qkv_kernel(
    const float* __restrict__ x,
    const float* __restrict__ Wq, const float* __restrict__ bq,
    const float* __restrict__ Wk, const float* __restrict__ bk,
    const float* __restrict__ Wv, const float* __restrict__ bv)
{
    __shared__ __align__(16) __half Wf[192 * 64];   // SW128, 128B rows
    __shared__ __align__(16) __half xB[64 * 128];   // SWX, 256B rows [c][n]
    __shared__ float sb[192];
    __shared__ float wvs[128];

    const int tid = threadIdx.x;
    const int b   = blockIdx.y;
    const int n0  = blockIdx.x * 128;
    const uint32_t wf_b = smem_u32(Wf);
    const uint32_t xb_b = smem_u32(xB);

    // ---- fill weights (fp32 -> fp16, LOG2E folded into Q rows) ----
    for (int e = tid; e < 1536; e += 384) {
        int oc = e >> 3, chv = e & 7;
        const float* wsrc;
        float scale = 1.f;
        if (oc < 64)       { wsrc = Wq + oc * 64;        scale = LOG2E; }
        else if (oc < 128) { wsrc = Wk + (oc - 64) * 64; }
        else               { wsrc = Wv + (oc - 128) * 64; }
        const float4 f0 = *(const float4*)(wsrc + chv * 8);
        const float4 f1 = *(const float4*)(wsrc + chv * 8 + 4);
        __half2 h[4];
        h[0] = __floats2half2_rn(f0.x * scale, f0.y * scale);
        h[1] = __floats2half2_rn(f0.z * scale, f0.w * scale);
        h[2] = __floats2half2_rn(f1.x * scale, f1.y * scale);
        h[3] = __floats2half2_rn(f1.z * scale, f1.w * scale);
        *(uint4*)((char*)Wf + SW128(oc * 128 + chv * 16)) = *(uint4*)h;
    }
    // ---- fill x tile [c][n] fp16 ----
    for (int e = tid; e < 1024; e += 384) {
        int c = e >> 4, ch = e & 15;
        const float* xp = x + (size_t)(b * 64 + c) * HW + n0 + ch * 8;
        const float4 f0 = *(const float4*)xp;
        const float4 f1 = *(const float4*)(xp + 4);
        __half2 h[4];
        h[0] = __floats2half2_rn(f0.x, f0.y);
        h[1] = __floats2half2_rn(f0.z, f0.w);
        h[2] = __floats2half2_rn(f1.x, f1.y);
        h[3] = __floats2half2_rn(f1.z, f1.w);
        *(uint4*)((char*)xB + SWX(c * 256 + ch * 16)) = *(uint4*)h;
    }
    if (tid < 192)
        sb[tid] = (tid < 64) ? bq[tid] * LOG2E
                 : (tid < 128) ? bk[tid - 64] : bv[tid - 128];
    if (tid < 128) wvs[tid] = g_w[b * HW + n0 + tid];
    __syncthreads();

    const int wid  = tid >> 5, lane = tid & 31;
    const int g    = lane >> 2, u = lane & 3;
    const int mt   = wid;                 // m16 tile (0..11)
    const int oc_b = mt * 16;

    // ---- A fragments (persist; 16 regs) ----
    uint32_t aW[4][4];
    #pragma unroll
    for (int ks = 0; ks < 4; ks++)
        LDMX4(aW[ks], wf_b + SW128((oc_b + (lane & 15)) * 128 +
                                   ks * 32 + (lane >> 4) * 16));

    float s[16][4];
    #pragma unroll
    for (int i = 0; i < 16; i++)
        s[i][0] = s[i][1] = s[i][2] = s[i][3] = 0.f;

    // ---- mainloop: 8 n16 blocks x 4 k-steps ----
    #pragma unroll
    for (int nt2 = 0; nt2 < 8; nt2++) {
        #pragma unroll
        for (int ks = 0; ks < 4; ks++) {
            uint32_t bb[4];
            LDMX4T(bb, xb_b + SWX((ks * 16 + (lane & 15)) * 256 +
                                  nt2 * 32 + (lane >> 4) * 16));
            MMA16816(s[2 * nt2],     aW[ks], bb[0], bb[1]);
            MMA16816(s[2 * nt2 + 1], aW[ks], bb[2], bb[3]);
        }
    }

    // ---- epilogue ----
    const float b0 = sb[oc_b + g], b1 = sb[oc_b + 8 + g];
    const bool isV = (mt >= 8);
    #pragma unroll
    for (int nt = 0; nt < 16; nt++) {
        const int nn = nt * 8 + 2 * u;
        float v00 = s[nt][0] + b0, v01 = s[nt][1] + b0;
        float v10 = s[nt][2] + b1, v11 = s[nt][3] + b1;
        if (isV) {
            const float w0 = wvs[nn], w1 = wvs[nn + 1];
            v00 *= w0; v01 *= w1; v10 *= w0; v11 *= w1;
        }
        uint32_t h0 = f16x2_pack(v00, v01);   // row oc_b+g,   n-pair
        uint32_t h1 = f16x2_pack(v10, v11);   // row oc_b+8+g, n-pair
        if (isV) {
            const size_t vb = (size_t)(b * 64 + (oc_b - 128) + g) * HW + n0 + nn;
            *(uint32_t*)(g_Vf + vb)          = h0;
            *(uint32_t*)(g_Vf + vb + 8 * HW) = h1;
        } else {
            // transpose octets in-register: thread now holds token n = nt*8+g,
            // channel pair (2u, 2u+1) [+8 for t1]
            uint32_t t0 = movm_trans(h0);
            uint32_t t1 = movm_trans(h1);
            const int n = nt * 8 + g;
            __half* dst = (mt < 4) ? g_Qf : g_Kf;
            const int cb = (mt < 4) ? oc_b : oc_b - 64;
            const size_t qb = (size_t)(b * HW + n0 + n) * 64 + cb + 2 * u;
            *(uint32_t*)(dst + qb)     = t0;
            *(uint32_t*)(dst + qb + 8) = t1;
        }
    }
}

// ================= kernel 3: fp16 flash attention (R11 proven) ============
#define OFF_QF 0
#define OFF_K  16384
#define OFF_V  49152
#define OFF_AW 81920
#define SMEM_BYTES 82944
#define OFF_OST0 0
#define OFF_OST1 32768
#define OFF_MSH  65536
#define OFF_DSH  66560

__global__ __launch_bounds__(512, 1) void flash_kernel(
    const float* __restrict__ x, const float* __restrict__ gamma,
    float* __restrict__ out)
{
    extern __shared__ char smem[];
    const uint32_t sbase = smem_u32(smem);
    const int tid  = threadIdx.x;
    const int lane = tid & 31, wid = tid >> 5;
    const int qg   = wid & 7;
    const int half = wid >> 3;
    const int g    = lane >> 2;
    const int u    = lane & 3;
    const int q0w  = qg * 16;
    const int b    = blockIdx.y;
    const int n0   = blockIdx.x * 128;

    {
        const uint4* Qg = (const uint4*)(g_Qf + ((size_t)(b * HW + n0)) * 64);
        const uint4* Kg = (const uint4*)(g_Kf + ((size_t)(b * HW)) * 64);
        for (int e = tid; e < 1024; e += 512) {
            int r = e >> 3, c8 = e & 7;
            uint32_t o = SW128(r * 128 + c8 * 16);
            *(uint4*)(smem + OFF_QF + o) = Qg[e];
            *(uint4*)(smem + OFF_K + o)  = Kg[e];
        }
        const __half* Vg = g_Vf + (size_t)b * 64 * HW;
        for (int e = tid; e < 1024; e += 512) {
            int c = e >> 4, j8 = e & 15;
            uint4 val = *(const uint4*)(Vg + (size_t)c * HW + j8 * 8);
            *(uint4*)(smem + OFF_V + (j8 >> 3) * 8192 +
                      SW128(c * 128 + (j8 & 7) * 16)) = val;
        }
        if (tid < 128) *(float*)(smem + OFF_AW + tid * 4) = fabsf(g_w[b * HW + tid]);
    }
    __syncthreads();

    float o[8][4];
    #pragma unroll
    for (int ct = 0; ct < 8; ct++)
        o[ct][0] = o[ct][1] = o[ct][2] = o[ct][3] = 0.f;
    float mrow0 = -1e30f, mrow1 = -1e30f, den0 = 0.f, den1 = 0.f;

    const int qrow = q0w + (lane & 15);

    for (int t = 0; t < 32; t++) {
        const int buf = t & 1;

        if (t < 31) {
            const int m1 = (t + 1) * 128, nb = buf ^ 1;
            const uint4* Kg = (const uint4*)(g_Kf + ((size_t)(b * HW + m1)) * 64);
            char* kb = smem + OFF_K + nb * 16384;
            for (int e = tid; e < 1024; e += 512) {
                int r = e >> 3, c8 = e & 7;
                *(uint4*)(kb + SW128(r * 128 + c8 * 16)) = Kg[e];
            }
            const __half* Vg = g_Vf + (size_t)b * 64 * HW + m1;
            char* vb = smem + OFF_V + nb * 16384;
            for (int e = tid; e < 1024; e += 512) {
                int c = e >> 4, j8 = e & 15;
                uint4 val = *(const uint4*)(Vg + (size_t)c * HW + j8 * 8);
                *(uint4*)(vb + (j8 >> 3) * 8192 +
                          SW128(c * 128 + (j8 & 7) * 16)) = val;
            }
            if (tid < 128)
                *(float*)(smem + OFF_AW + nb * 512 + tid * 4) =
                    fabsf(g_w[b * HW + m1 + tid]);
        }

        const uint32_t k_b  = sbase + OFF_K + buf * 16384;
        const float*   awp  = (const float*)(smem + OFF_AW + buf * 512);

        uint32_t qf[4][4];
        #pragma unroll
        for (int ks = 0; ks < 4; ks++) {
            const uint32_t cb = ks * 32 + (lane >> 4) * 16;
            LDMX4(qf[ks], sbase + OFF_QF + SW128(qrow * 128 + cb));
        }

        float s[8][4];
        #pragma unroll
        for (int i = 0; i < 8; i++)
            s[i][0] = s[i][1] = s[i][2] = s[i][3] = 0.f;

        #pragma unroll
        for (int i = 0; i < 8; i++) {
            const int nt = half * 8 + i;
            const uint32_t roff = (nt * 8 + (lane & 7)) * 128 + (lane >> 3) * 16;
            uint32_t bh[8];
            LDMX4(bh,     k_b + SW128(roff));
            LDMX4(bh + 4, k_b + SW128(roff + 64));
            #pragma unroll
            for (int ks = 0; ks < 4; ks++)
                MMA16816(s[i], qf[ks], bh[2 * ks], bh[2 * ks + 1]);
        }

        float mx0 = s[0][0], mx1 = s[0][2];
        #pragma unroll
        for (int i = 0; i < 8; i++) {
            mx0 = fmaxf(mx0, fmaxf(s[i][0], s[i][1]));
            mx1 = fmaxf(mx1, fmaxf(s[i][2], s[i][3]));
        }
        mx0 = fmaxf(mx0, __shfl_xor_sync(0xffffffffu, mx0, 1));
        mx0 = fmaxf(mx0, __shfl_xor_sync(0xffffffffu, mx0, 2));
        mx1 = fmaxf(mx1, __shfl_xor_sync(0xffffffffu, mx1, 1));
        mx1 = fmaxf(mx1, __shfl_xor_sync(0xffffffffu, mx1, 2));

        const float mn0 = fmaxf(mrow0, mx0), mn1 = fmaxf(mrow1, mx1);
        const float cr0 = ex2f(mrow0 - mn0), cr1 = ex2f(mrow1 - mn1);
        mrow0 = mn0; mrow1 = mn1;

        float ws0 = 0.f, ws1 = 0.f;
        uint32_t aP[4][4];
        #pragma unroll
        for (int i = 0; i < 8; i++) {
            const float2 aw = *(const float2*)&awp[half * 64 + i * 8 + 2 * u];
            uint32_t h01 = ex2_h2(f16x2_pack(s[i][0] - mn0, s[i][1] - mn0));
            uint32_t h23 = ex2_h2(f16x2_pack(s[i][2] - mn1, s[i][3] - mn1));
            aP[i >> 1][(i & 1) * 2]     = h01;
            aP[i >> 1][(i & 1) * 2 + 1] = h23;
            const float2 p01 = __half22float2(*(const __half2*)&h01);
            const float2 p23 = __half22float2(*(const __half2*)&h23);
            ws0 += p01.x * aw.x + p01.y * aw.y;
            ws1 += p23.x * aw.x + p23.y * aw.y;
        }
        ws0 += __shfl_xor_sync(0xffffffffu, ws0, 1);
        ws0 += __shfl_xor_sync(0xffffffffu, ws0, 2);
        ws1 += __shfl_xor_sync(0xffffffffu, ws1, 1);
        ws1 += __shfl_xor_sync(0xffffffffu, ws1, 2);
        den0 = den0 * cr0 + ws0;
        den1 = den1 * cr1 + ws1;

        #pragma unroll
        for (int ct = 0; ct < 8; ct++) {
            o[ct][0] *= cr0; o[ct][1] *= cr0;
            o[ct][2] *= cr1; o[ct][3] *= cr1;
        }

        const uint32_t v_b = sbase + OFF_V + buf * 16384 + half * 8192;
        #pragma unroll
        for (int ct = 0; ct < 8; ct++) {
            const uint32_t roff = (ct * 8 + (lane & 7)) * 128 + (lane >> 3) * 16;
            uint32_t vb[8];
            LDMX4(vb,     v_b + SW128(roff));
            LDMX4(vb + 4, v_b + SW128(roff + 64));
            #pragma unroll
            for (int j = 0; j < 4; j++)
                MMA16816(o[ct], aP[j], vb[2 * j], vb[2 * j + 1]);
        }
        __syncthreads();
    }

    const int r0 = q0w + g, r1 = q0w + g + 8;
    float* msh = (float*)(smem + OFF_MSH);
    float* dsh = (float*)(smem + OFF_DSH);
    if (u == 0) {
        msh[half * 128 + r0] = mrow0;  msh[half * 128 + r1] = mrow1;
        dsh[half * 128 + r0] = den0;   dsh[half * 128 + r1] = den1;
    }
    __syncthreads();

    const float g0 = gamma[0];
    const float mo0 = msh[(1 - half) * 128 + r0], do0 = dsh[(1 - half) * 128 + r0];
    const float mo1 = msh[(1 - half) * 128 + r1], do1 = dsh[(1 - half) * 128 + r1];
    const float mf0 = fmaxf(mrow0, mo0), mf1 = fmaxf(mrow1, mo1);
    const float sm0 = ex2f(mrow0 - mf0), sm1 = ex2f(mrow1 - mf1);
    const float df0 = den0 * sm0 + do0 * ex2f(mo0 - mf0);
    const float df1 = den1 * sm1 + do1 * ex2f(mo1 - mf1);
    const float inv0 = g0 * sm0 / df0, inv1 = g0 * sm1 / df1;

    float* Ost = (float*)(smem + (half ? OFF_OST1 : OFF_OST0));
    #pragma unroll
    for (int ct = 0; ct < 8; ct++) {
        const int c = ct * 8 + 2 * u;
        Ost[c * 128 + r0]       = o[ct][0] * inv0;
        Ost[(c + 1) * 128 + r0] = o[ct][1] * inv0;
        Ost[c * 128 + r1]       = o[ct][2] * inv1;
        Ost[(c + 1) * 128 + r1] = o[ct][3] * inv1;
    }
    __syncthreads();

    const float* O0 = (const float*)(smem + OFF_OST0);
    const float* O1 = (const float*)(smem + OFF_OST1);
    for (int e = tid; e < 2048; e += 512) {
        const int c = e >> 5, q4 = (e & 31) * 4;
        const int idx = c * 128 + q4;
        float4 a = *(const float4*)&O0[idx];
        const float4 bb = *(const float4*)&O1[idx];
        const size_t off = (size_t)(b * 64 + c) * HW + n0 + q4;
        const float4 xv = *(const float4*)&x[off];
        a.x += bb.x + xv.x; a.y += bb.y + xv.y;
        a.z += bb.z + xv.z; a.w += bb.w + xv.w;
        *(float4*)&out[off] = a;
    }
}

// ================= launch =================
extern "C" void kernel_launch(void* const* d_in, const int* in_sizes, int n_in,
                              void* d_out, int out_size)
{
    (void)in_sizes; (void)n_in; (void)out_size;
    const float* x       = (const float*)d_in[0];
    const float* Wq      = (const float*)d_in[1];
    const float* bq      = (const float*)d_in[2];
    const float* Wk      = (const float*)d_in[3];
    const float* bk      = (const float*)d_in[4];
    const float* Wv      = (const float*)d_in[5];
    const float* bv      = (const float*)d_in[6];
    const float* We1     = (const float*)d_in[7];
    const float* be1     = (const float*)d_in[8];
    const float* bn_w    = (const float*)d_in[9];
    const float* bn_b    = (const float*)d_in[10];
    const float* bn_mean = (const float*)d_in[11];
    const float* bn_var  = (const float*)d_in[12];
    const float* We2     = (const float*)d_in[13];
    const float* be2     = (const float*)d_in[14];
    const float* gamma   = (const float*)d_in[15];
    const float* beta    = (const float*)d_in[16];
    float* out = (float*)d_out;

    cudaFuncSetAttribute(edge_kernel, cudaFuncAttributeMaxDynamicSharedMemorySize,
                         EDGE_SMEM);
    edge_kernel<<<dim3(32, NB), 256, EDGE_SMEM>>>(x, We1, be1, bn_w, bn_b,
                                                  bn_mean, bn_var, We2, be2, beta);
    qkv_kernel<<<dim3(32, NB), 384>>>(x, Wq, bq, Wk, bk, Wv, bv);

    cudaFuncSetAttribute(flash_kernel, cudaFuncAttributeMaxDynamicSharedMemorySize,
                         SMEM_BYTES);
    flash_kernel<<<dim3(32, NB), 512, SMEM_BYTES>>>(x, gamma, out);
}